// round 1
// baseline (speedup 1.0000x reference)
#include <cuda_runtime.h>
#include <math.h>

#define NB 2
#define NS 2048
#define NE 128
#define NH 16
#define ND 128
#define NINNER 2048
#define NROWS 4096
#define HALF 64

// Scratch (static device allocations are allowed)
__device__ float  g_Q[NB*NH*NS*ND];
__device__ float  g_K[NB*NH*NS*ND];
__device__ float  g_V[NB*NH*NS*ND];
__device__ float  g_O[NB*NH*NS*ND];
__device__ float2 g_rope[NS*HALF];   // (cos, sin) per (s, pair)

// ---------------------------------------------------------------------------
// Kernel 0: RoPE table (double-precision, computed fresh each call)
// ---------------------------------------------------------------------------
__global__ void rope_table_kernel() {
    int idx = blockIdx.x * 256 + threadIdx.x;
    if (idx >= NS * HALF) return;
    int s = idx / HALF, p = idx % HALF;
    double inv = exp(-(double)p * (log(10000.0) / 64.0));
    double a = (double)s * inv;
    g_rope[idx] = make_float2((float)cos(a), (float)sin(a));
}

// ---------------------------------------------------------------------------
// Kernel 1: fused QKV projection GEMM + RoPE epilogue.
// C[row, col] = sum_k q[row, k] * W[k, col];  row=(b,s) in 4096, col in 2048.
// Output layout [B,H,S,D]. grid.z in {0:Q(rope),1:K(rope),2:V}.
// Block tile 64x64, K=128 fully resident in smem. 256 threads, 4x4 microtile.
// ---------------------------------------------------------------------------
__global__ __launch_bounds__(256) void proj_kernel(
    const float* __restrict__ q, const float* __restrict__ Wq,
    const float* __restrict__ Wk, const float* __restrict__ Wv)
{
    extern __shared__ float sm[];
    float* At = sm;             // [128][64]  A^T
    float* Bs = sm + 128 * 64;  // [128][64]

    int z = blockIdx.z;
    const float* W = (z == 0) ? Wq : (z == 1) ? Wk : Wv;
    float* dst = (z == 0) ? g_Q : (z == 1) ? g_K : g_V;
    bool do_rope = (z < 2);

    int row0 = blockIdx.y * 64;
    int col0 = blockIdx.x * 64;
    int tid = threadIdx.x;

    // Load A tile transposed (coalesced global read, transposed smem store)
    for (int i = tid * 4; i < 64 * 128; i += 1024) {
        int r = i >> 7, k = i & 127;
        float4 v = *(const float4*)&q[(size_t)(row0 + r) * NE + k];
        At[(k + 0) * 64 + r] = v.x;
        At[(k + 1) * 64 + r] = v.y;
        At[(k + 2) * 64 + r] = v.z;
        At[(k + 3) * 64 + r] = v.w;
    }
    // Load B tile natural (W is k-major already)
    for (int i = tid * 4; i < 128 * 64; i += 1024) {
        int k = i >> 6, c = i & 63;
        *(float4*)&Bs[k * 64 + c] = *(const float4*)&W[(size_t)k * NINNER + col0 + c];
    }
    __syncthreads();

    int ty = tid / 16, tx = tid % 16;
    float acc[4][4] = {};
    #pragma unroll 4
    for (int k = 0; k < 128; k++) {
        float4 av = *(float4*)&At[k * 64 + ty * 4];
        float4 bv = *(float4*)&Bs[k * 64 + tx * 4];
        float a[4] = {av.x, av.y, av.z, av.w};
        float b[4] = {bv.x, bv.y, bv.z, bv.w};
        #pragma unroll
        for (int j = 0; j < 4; j++)
            #pragma unroll
            for (int i = 0; i < 4; i++)
                acc[j][i] += a[j] * b[i];
    }

    int colbase = col0 + tx * 4;          // 4 consecutive cols, same head
    int h = colbase / ND;
    int d0 = colbase % ND;
    int p0 = d0 >> 1;
    #pragma unroll
    for (int j = 0; j < 4; j++) {
        int row = row0 + ty * 4 + j;
        int b = row >> 11, s = row & (NS - 1);
        float v0 = acc[j][0], v1 = acc[j][1], v2 = acc[j][2], v3 = acc[j][3];
        if (do_rope) {
            float2 cs0 = g_rope[s * HALF + p0];
            float2 cs1 = g_rope[s * HALF + p0 + 1];
            float r0 = v0 * cs0.x - v1 * cs0.y;
            float r1 = v1 * cs0.x + v0 * cs0.y;
            float r2 = v2 * cs1.x - v3 * cs1.y;
            float r3 = v3 * cs1.x + v2 * cs1.y;
            v0 = r0; v1 = r1; v2 = r2; v3 = r3;
        }
        *(float4*)&dst[((size_t)(b * NH + h) * NS + s) * ND + d0] =
            make_float4(v0, v1, v2, v3);
    }
}

// ---------------------------------------------------------------------------
// Kernel 2: causal flash attention, fp32.
// Block = (qt, h, b): 64 query rows, streams 64-key tiles 0..qt.
// smem: Q^T[128][64], K^T[128][64], V[64][128], P^T[64][65] = 112.25 KB
// 256 threads: S-phase 4x4 microtile (16x16 grid), PV-phase 4 rows x 8 cols.
// ---------------------------------------------------------------------------
__global__ __launch_bounds__(256, 2) void attn_kernel() {
    extern __shared__ float sm[];
    float* Qt = sm;            // [128][64]
    float* Kt = sm + 8192;     // [128][64]
    float* Vs = sm + 16384;    // [64][128]
    float* Pt = sm + 24576;    // [64][65]

    int qt = blockIdx.x, h = blockIdx.y, b = blockIdx.z;
    const float* Qg = &g_Q[((size_t)(b * NH + h) * NS + qt * 64) * ND];
    const float* Kg = &g_K[(size_t)(b * NH + h) * NS * ND];
    const float* Vg = &g_V[(size_t)(b * NH + h) * NS * ND];

    int tid = threadIdx.x, ty = tid / 16, tx = tid % 16;
    const float scale = 0.08838834764831845f;   // 1/sqrt(128)

    // Q tile, transposed, pre-scaled
    for (int i = tid * 4; i < 64 * 128; i += 1024) {
        int r = i >> 7, k = i & 127;
        float4 v = *(const float4*)&Qg[(size_t)r * ND + k];
        Qt[(k + 0) * 64 + r] = v.x * scale;
        Qt[(k + 1) * 64 + r] = v.y * scale;
        Qt[(k + 2) * 64 + r] = v.z * scale;
        Qt[(k + 3) * 64 + r] = v.w * scale;
    }

    float acc[4][8] = {};
    float m[4], l[4];
    #pragma unroll
    for (int j = 0; j < 4; j++) { m[j] = -INFINITY; l[j] = 0.0f; }

    for (int kt = 0; kt <= qt; kt++) {
        __syncthreads();   // protect Kt/Vs/Pt from previous iteration readers
        const float* Kgt = Kg + (size_t)kt * 64 * ND;
        const float* Vgt = Vg + (size_t)kt * 64 * ND;
        for (int i = tid * 4; i < 64 * 128; i += 1024) {
            int r = i >> 7, k = i & 127;
            float4 v = *(const float4*)&Kgt[(size_t)r * ND + k];
            Kt[(k + 0) * 64 + r] = v.x;
            Kt[(k + 1) * 64 + r] = v.y;
            Kt[(k + 2) * 64 + r] = v.z;
            Kt[(k + 3) * 64 + r] = v.w;
            *(float4*)&Vs[i] = *(const float4*)&Vgt[i];
        }
        __syncthreads();

        // S = (Q*scale) @ K^T  -> 4x4 fragment
        float sf[4][4] = {};
        #pragma unroll 2
        for (int k = 0; k < 128; k++) {
            float4 av = *(float4*)&Qt[k * 64 + ty * 4];
            float4 bv = *(float4*)&Kt[k * 64 + tx * 4];
            float a[4] = {av.x, av.y, av.z, av.w};
            float bb[4] = {bv.x, bv.y, bv.z, bv.w};
            #pragma unroll
            for (int j = 0; j < 4; j++)
                #pragma unroll
                for (int i = 0; i < 4; i++)
                    sf[j][i] += a[j] * bb[i];
        }

        if (kt == qt) {   // causal mask, diagonal tile only
            #pragma unroll
            for (int j = 0; j < 4; j++)
                #pragma unroll
                for (int i = 0; i < 4; i++)
                    if (tx * 4 + i > ty * 4 + j) sf[j][i] = -INFINITY;
        }

        // Online softmax (reduce across the 16 tx lanes sharing a row)
        #pragma unroll
        for (int j = 0; j < 4; j++) {
            float mt = fmaxf(fmaxf(sf[j][0], sf[j][1]), fmaxf(sf[j][2], sf[j][3]));
            #pragma unroll
            for (int o = 1; o < 16; o <<= 1)
                mt = fmaxf(mt, __shfl_xor_sync(0xFFFFFFFFu, mt, o));
            float mnew = fmaxf(m[j], mt);
            float alpha = __expf(m[j] - mnew);
            float r = 0.0f;
            #pragma unroll
            for (int i = 0; i < 4; i++) {
                float p = __expf(sf[j][i] - mnew);
                sf[j][i] = p;
                r += p;
            }
            #pragma unroll
            for (int o = 1; o < 16; o <<= 1)
                r += __shfl_xor_sync(0xFFFFFFFFu, r, o);
            l[j] = l[j] * alpha + r;
            m[j] = mnew;
            #pragma unroll
            for (int c = 0; c < 8; c++) acc[j][c] *= alpha;
        }

        // P^T to shared (stride 65 kills bank conflicts)
        #pragma unroll
        for (int i = 0; i < 4; i++)
            #pragma unroll
            for (int j = 0; j < 4; j++)
                Pt[(tx * 4 + i) * 65 + ty * 4 + j] = sf[j][i];
        __syncthreads();

        // O += P @ V
        #pragma unroll 2
        for (int c = 0; c < 64; c++) {
            float p0 = Pt[c * 65 + ty * 4 + 0];
            float p1 = Pt[c * 65 + ty * 4 + 1];
            float p2 = Pt[c * 65 + ty * 4 + 2];
            float p3 = Pt[c * 65 + ty * 4 + 3];
            float4 va = *(float4*)&Vs[c * 128 + tx * 8];
            float4 vb = *(float4*)&Vs[c * 128 + tx * 8 + 4];
            float v[8] = {va.x, va.y, va.z, va.w, vb.x, vb.y, vb.z, vb.w};
            float p[4] = {p0, p1, p2, p3};
            #pragma unroll
            for (int j = 0; j < 4; j++)
                #pragma unroll
                for (int cc = 0; cc < 8; cc++)
                    acc[j][cc] += p[j] * v[cc];
        }
    }

    float* Og = &g_O[((size_t)(b * NH + h) * NS + qt * 64) * ND];
    #pragma unroll
    for (int j = 0; j < 4; j++) {
        float inv = 1.0f / l[j];
        *(float4*)&Og[(size_t)(ty * 4 + j) * ND + tx * 8] =
            make_float4(acc[j][0] * inv, acc[j][1] * inv, acc[j][2] * inv, acc[j][3] * inv);
        *(float4*)&Og[(size_t)(ty * 4 + j) * ND + tx * 8 + 4] =
            make_float4(acc[j][4] * inv, acc[j][5] * inv, acc[j][6] * inv, acc[j][7] * inv);
    }
}

// ---------------------------------------------------------------------------
// Kernel 3: output projection. out[row, e] = sum_k O[row, k] * Wo[k, e]
// M=4096, N=128, K=2048. Block tile 64x64, K chunks of 32.
// ---------------------------------------------------------------------------
__global__ __launch_bounds__(256) void out_kernel(
    const float* __restrict__ Wo, float* __restrict__ out)
{
    __shared__ float At[32 * 64];   // [k][r]
    __shared__ float Bs[32 * 64];   // [k][c]

    int row0 = blockIdx.y * 64, col0 = blockIdx.x * 64;
    int tid = threadIdx.x, ty = tid / 16, tx = tid % 16;
    float acc[4][4] = {};

    for (int k0 = 0; k0 < NINNER; k0 += 32) {
        __syncthreads();
        for (int i = tid * 4; i < 64 * 32; i += 1024) {
            int r = i >> 5, k = i & 31;
            int row = row0 + r;
            int b = row >> 11, s = row & (NS - 1);
            int kk = k0 + k;
            int h = kk >> 7, d = kk & 127;
            float4 v = *(const float4*)&g_O[((size_t)(b * NH + h) * NS + s) * ND + d];
            At[(k + 0) * 64 + r] = v.x;
            At[(k + 1) * 64 + r] = v.y;
            At[(k + 2) * 64 + r] = v.z;
            At[(k + 3) * 64 + r] = v.w;
        }
        for (int i = tid * 4; i < 32 * 64; i += 1024) {
            int k = i >> 6, c = i & 63;
            *(float4*)&Bs[k * 64 + c] = *(const float4*)&Wo[(size_t)(k0 + k) * NE + col0 + c];
        }
        __syncthreads();
        #pragma unroll
        for (int k = 0; k < 32; k++) {
            float4 av = *(float4*)&At[k * 64 + ty * 4];
            float4 bv = *(float4*)&Bs[k * 64 + tx * 4];
            float a[4] = {av.x, av.y, av.z, av.w};
            float bb[4] = {bv.x, bv.y, bv.z, bv.w};
            #pragma unroll
            for (int j = 0; j < 4; j++)
                #pragma unroll
                for (int i = 0; i < 4; i++)
                    acc[j][i] += a[j] * bb[i];
        }
    }

    #pragma unroll
    for (int j = 0; j < 4; j++) {
        int row = row0 + ty * 4 + j;
        *(float4*)&out[(size_t)row * NE + col0 + tx * 4] =
            make_float4(acc[j][0], acc[j][1], acc[j][2], acc[j][3]);
    }
}

// ---------------------------------------------------------------------------
extern "C" void kernel_launch(void* const* d_in, const int* in_sizes, int n_in,
                              void* d_out, int out_size) {
    const float* q  = (const float*)d_in[0];
    const float* Wq = (const float*)d_in[1];
    const float* Wk = (const float*)d_in[2];
    const float* Wv = (const float*)d_in[3];
    const float* Wo = (const float*)d_in[4];
    float* out = (float*)d_out;

    cudaFuncSetAttribute(proj_kernel, cudaFuncAttributeMaxDynamicSharedMemorySize, 65536);
    cudaFuncSetAttribute(attn_kernel, cudaFuncAttributeMaxDynamicSharedMemorySize, 114944);

    rope_table_kernel<<<(NS * HALF + 255) / 256, 256>>>();

    dim3 g1(NINNER / 64, NROWS / 64, 3);
    proj_kernel<<<g1, 256, 65536>>>(q, Wq, Wk, Wv);

    dim3 g2(NS / 64, NH, NB);
    attn_kernel<<<g2, 256, 114944>>>();

    dim3 g3(NE / 64, NROWS / 64);
    out_kernel<<<g3, 256>>>(Wo, out);
}

// round 4
// speedup vs baseline: 2.8361x; 2.8361x over previous
#include <cuda_runtime.h>
#include <math.h>
#include <stdint.h>

#define NB 2
#define NS 2048
#define NE 128
#define NH 16
#define ND 128
#define NINNER 2048
#define NROWS 4096
#define HALF 64

// Scratch
__device__ float  g_Q[NB*NH*NS*ND];
__device__ float  g_K[NB*NH*NS*ND];
__device__ float  g_V[NB*NH*NS*ND];
__device__ float  g_O[NB*NH*NS*ND];
__device__ float2 g_rope[NS*HALF];

// ---------------------------------------------------------------------------
__global__ void rope_table_kernel() {
    int idx = blockIdx.x * 256 + threadIdx.x;
    if (idx >= NS * HALF) return;
    int s = idx / HALF, p = idx % HALF;
    double inv = exp(-(double)p * (log(10000.0) / 64.0));
    double a = (double)s * inv;
    g_rope[idx] = make_float2((float)cos(a), (float)sin(a));
}

// ---------------------------------------------------------------------------
// Kernel 1: fused QKV projection GEMM + RoPE epilogue (fp32).
// ---------------------------------------------------------------------------
__global__ __launch_bounds__(256) void proj_kernel(
    const float* __restrict__ q, const float* __restrict__ Wq,
    const float* __restrict__ Wk, const float* __restrict__ Wv)
{
    extern __shared__ float sm[];
    float* At = sm;
    float* Bs = sm + 128 * 64;

    int z = blockIdx.z;
    const float* W = (z == 0) ? Wq : (z == 1) ? Wk : Wv;
    float* dst = (z == 0) ? g_Q : (z == 1) ? g_K : g_V;
    bool do_rope = (z < 2);

    int row0 = blockIdx.y * 64;
    int col0 = blockIdx.x * 64;
    int tid = threadIdx.x;

    for (int i = tid * 4; i < 64 * 128; i += 1024) {
        int r = i >> 7, k = i & 127;
        float4 v = *(const float4*)&q[(size_t)(row0 + r) * NE + k];
        At[(k + 0) * 64 + r] = v.x;
        At[(k + 1) * 64 + r] = v.y;
        At[(k + 2) * 64 + r] = v.z;
        At[(k + 3) * 64 + r] = v.w;
    }
    for (int i = tid * 4; i < 128 * 64; i += 1024) {
        int k = i >> 6, c = i & 63;
        *(float4*)&Bs[k * 64 + c] = *(const float4*)&W[(size_t)k * NINNER + col0 + c];
    }
    __syncthreads();

    int ty = tid / 16, tx = tid % 16;
    float acc[4][4] = {};
    #pragma unroll 4
    for (int k = 0; k < 128; k++) {
        float4 av = *(float4*)&At[k * 64 + ty * 4];
        float4 bv = *(float4*)&Bs[k * 64 + tx * 4];
        float a[4] = {av.x, av.y, av.z, av.w};
        float b[4] = {bv.x, bv.y, bv.z, bv.w};
        #pragma unroll
        for (int j = 0; j < 4; j++)
            #pragma unroll
            for (int i = 0; i < 4; i++)
                acc[j][i] += a[j] * b[i];
    }

    int colbase = col0 + tx * 4;
    int h = colbase / ND;
    int d0 = colbase % ND;
    int p0 = d0 >> 1;
    #pragma unroll
    for (int j = 0; j < 4; j++) {
        int row = row0 + ty * 4 + j;
        int b = row >> 11, s = row & (NS - 1);
        float v0 = acc[j][0], v1 = acc[j][1], v2 = acc[j][2], v3 = acc[j][3];
        if (do_rope) {
            float2 cs0 = g_rope[s * HALF + p0];
            float2 cs1 = g_rope[s * HALF + p0 + 1];
            float r0 = v0 * cs0.x - v1 * cs0.y;
            float r1 = v1 * cs0.x + v0 * cs0.y;
            float r2 = v2 * cs1.x - v3 * cs1.y;
            float r3 = v3 * cs1.x + v2 * cs1.y;
            v0 = r0; v1 = r1; v2 = r2; v3 = r3;
        }
        *(float4*)&dst[((size_t)(b * NH + h) * NS + s) * ND + d0] =
            make_float4(v0, v1, v2, v3);
    }
}

// ---------------------------------------------------------------------------
// tf32 mma helpers
// ---------------------------------------------------------------------------
__device__ __forceinline__ uint32_t f2tf(float f) {
    uint32_t u;
    asm("cvt.rna.tf32.f32 %0, %1;" : "=r"(u) : "f"(f));
    return u;
}
__device__ __forceinline__ float f2tf_f(float f) {
    return __uint_as_float(f2tf(f));
}
__device__ __forceinline__ void mma8(float* c, uint32_t a0, uint32_t a1,
                                     uint32_t a2, uint32_t a3,
                                     uint32_t b0, uint32_t b1) {
    asm("mma.sync.aligned.m16n8k8.row.col.f32.tf32.tf32.f32 "
        "{%0,%1,%2,%3},{%4,%5,%6,%7},{%8,%9},{%0,%1,%2,%3};"
        : "+f"(c[0]), "+f"(c[1]), "+f"(c[2]), "+f"(c[3])
        : "r"(a0), "r"(a1), "r"(a2), "r"(a3), "r"(b0), "r"(b1));
}
__device__ __forceinline__ float ex2(float x) {
    float y;
    asm("ex2.approx.f32 %0, %1;" : "=f"(y) : "f"(x));
    return y;
}

// ---------------------------------------------------------------------------
// Kernel 2: causal flash attention, tf32 tensor cores.
// CTA = 256 threads (8 warps). Q tile 128 rows; each warp owns 16 rows, full
// 64-col K tiles. Strides: Qs/Ks 132, Vs 136, Pt 68 (conflict-free fragments).
// ---------------------------------------------------------------------------
#define QS_OFF 0
#define KS_OFF (128*132)
#define VS_OFF (KS_OFF + 64*132)
#define PT_OFF (VS_OFF + 64*136)
#define ATTN_SMEM ((PT_OFF + 128*68) * 4)

__global__ __launch_bounds__(256, 1) void attn_kernel() {
    extern __shared__ float sm[];
    float* Qs = sm + QS_OFF;   // [128][132]
    float* Ks = sm + KS_OFF;   // [64][132]
    float* Vs = sm + VS_OFF;   // [64][136]
    float* Pt = sm + PT_OFF;   // [128][68]

    int qt = gridDim.x - 1 - blockIdx.x;   // heavy tiles first
    int h = blockIdx.y, b = blockIdx.z;
    const float* Qg = &g_Q[((size_t)(b * NH + h) * NS + qt * 128) * ND];
    const float* Kg = &g_K[(size_t)(b * NH + h) * NS * ND];
    const float* Vg = &g_V[(size_t)(b * NH + h) * NS * ND];

    int tid = threadIdx.x;
    int wid = tid >> 5, lane = tid & 31;
    int lg = lane >> 2;        // group (row within 8)
    int lc = lane & 3;         // col index within quad

    const float qscale = 0.08838834764831845f * 1.4426950408889634f;

    // Stage Q (pre-scaled, tf32-rounded)
    for (int i = tid * 4; i < 128 * 128; i += 1024) {
        int r = i >> 7, c = i & 127;
        float4 v = *(const float4*)&Qg[(size_t)r * ND + c];
        float* d = &Qs[r * 132 + c];
        d[0] = f2tf_f(v.x * qscale);
        d[1] = f2tf_f(v.y * qscale);
        d[2] = f2tf_f(v.z * qscale);
        d[3] = f2tf_f(v.w * qscale);
    }
    __syncthreads();

    float oacc[16][4] = {};
    float m0 = -1e30f, m1 = -1e30f, l0 = 0.0f, l1 = 0.0f;

    int row_base = wid * 16 + lg;
    int row_g0 = qt * 128 + row_base;
    int row_g1 = row_g0 + 8;

    int nkt = 2 * qt + 2;
    for (int kt = 0; kt < nkt; kt++) {
        __syncthreads();
        const float* Kgt = Kg + (size_t)kt * 64 * ND;
        const float* Vgt = Vg + (size_t)kt * 64 * ND;
        for (int i = tid * 4; i < 64 * 128; i += 1024) {
            int r = i >> 7, c = i & 127;
            float4 kv = *(const float4*)&Kgt[(size_t)r * ND + c];
            float4 vv = *(const float4*)&Vgt[(size_t)r * ND + c];
            float* dk = &Ks[r * 132 + c];
            dk[0] = f2tf_f(kv.x); dk[1] = f2tf_f(kv.y);
            dk[2] = f2tf_f(kv.z); dk[3] = f2tf_f(kv.w);
            float* dv = &Vs[r * 136 + c];
            dv[0] = f2tf_f(vv.x); dv[1] = f2tf_f(vv.y);
            dv[2] = f2tf_f(vv.z); dv[3] = f2tf_f(vv.w);
        }
        __syncthreads();

        // ---- S = Q @ K^T (16 rows x 64 cols per warp) ----
        float sacc[8][4] = {};
        #pragma unroll
        for (int ks = 0; ks < 16; ks++) {
            const float* qrow = &Qs[(wid * 16 + lg) * 132 + ks * 8 + lc];
            uint32_t a0 = __float_as_uint(qrow[0]);
            uint32_t a1 = __float_as_uint(qrow[8 * 132]);
            uint32_t a2 = __float_as_uint(qrow[4]);
            uint32_t a3 = __float_as_uint(qrow[8 * 132 + 4]);
            #pragma unroll
            for (int nb = 0; nb < 8; nb++) {
                const float* krow = &Ks[(nb * 8 + lg) * 132 + ks * 8 + lc];
                uint32_t b0 = __float_as_uint(krow[0]);
                uint32_t b1 = __float_as_uint(krow[4]);
                mma8(sacc[nb], a0, a1, a2, a3, b0, b1);
            }
        }

        // ---- causal mask (only last two K tiles can cross the diagonal) ----
        if (kt >= 2 * qt) {
            #pragma unroll
            for (int nb = 0; nb < 8; nb++) {
                int col_g = kt * 64 + nb * 8 + 2 * lc;
                if (col_g     > row_g0) sacc[nb][0] = -1e30f;
                if (col_g + 1 > row_g0) sacc[nb][1] = -1e30f;
                if (col_g     > row_g1) sacc[nb][2] = -1e30f;
                if (col_g + 1 > row_g1) sacc[nb][3] = -1e30f;
            }
        }

        // ---- online softmax (log2 domain) ----
        float mt0 = -1e30f, mt1 = -1e30f;
        #pragma unroll
        for (int nb = 0; nb < 8; nb++) {
            mt0 = fmaxf(mt0, fmaxf(sacc[nb][0], sacc[nb][1]));
            mt1 = fmaxf(mt1, fmaxf(sacc[nb][2], sacc[nb][3]));
        }
        mt0 = fmaxf(mt0, __shfl_xor_sync(0xFFFFFFFFu, mt0, 1));
        mt0 = fmaxf(mt0, __shfl_xor_sync(0xFFFFFFFFu, mt0, 2));
        mt1 = fmaxf(mt1, __shfl_xor_sync(0xFFFFFFFFu, mt1, 1));
        mt1 = fmaxf(mt1, __shfl_xor_sync(0xFFFFFFFFu, mt1, 2));
        float mn0 = fmaxf(m0, mt0), mn1 = fmaxf(m1, mt1);
        float al0 = ex2(m0 - mn0), al1 = ex2(m1 - mn1);
        m0 = mn0; m1 = mn1;

        float r0 = 0.0f, r1 = 0.0f;
        #pragma unroll
        for (int nb = 0; nb < 8; nb++) {
            float p0 = ex2(sacc[nb][0] - mn0);
            float p1 = ex2(sacc[nb][1] - mn0);
            float p2 = ex2(sacc[nb][2] - mn1);
            float p3 = ex2(sacc[nb][3] - mn1);
            r0 += p0 + p1; r1 += p2 + p3;
            *(float2*)&Pt[(wid * 16 + lg) * 68 + nb * 8 + 2 * lc] =
                make_float2(f2tf_f(p0), f2tf_f(p1));
            *(float2*)&Pt[(wid * 16 + lg + 8) * 68 + nb * 8 + 2 * lc] =
                make_float2(f2tf_f(p2), f2tf_f(p3));
        }
        r0 += __shfl_xor_sync(0xFFFFFFFFu, r0, 1);
        r0 += __shfl_xor_sync(0xFFFFFFFFu, r0, 2);
        r1 += __shfl_xor_sync(0xFFFFFFFFu, r1, 1);
        r1 += __shfl_xor_sync(0xFFFFFFFFu, r1, 2);
        l0 = l0 * al0 + r0;
        l1 = l1 * al1 + r1;

        // rescale O
        #pragma unroll
        for (int nb = 0; nb < 16; nb++) {
            oacc[nb][0] *= al0; oacc[nb][1] *= al0;
            oacc[nb][2] *= al1; oacc[nb][3] *= al1;
        }
        __syncwarp();

        // ---- O += P @ V (16 rows x 128 cols per warp) ----
        #pragma unroll
        for (int ks = 0; ks < 8; ks++) {
            const float* prow = &Pt[(wid * 16 + lg) * 68 + ks * 8 + lc];
            uint32_t a0 = __float_as_uint(prow[0]);
            uint32_t a1 = __float_as_uint(prow[8 * 68]);
            uint32_t a2 = __float_as_uint(prow[4]);
            uint32_t a3 = __float_as_uint(prow[8 * 68 + 4]);
            #pragma unroll
            for (int nb = 0; nb < 16; nb++) {
                const float* vrow = &Vs[(ks * 8 + lc) * 136 + nb * 8 + lg];
                uint32_t b0 = __float_as_uint(vrow[0]);
                uint32_t b1 = __float_as_uint(vrow[4 * 136]);
                mma8(oacc[nb], a0, a1, a2, a3, b0, b1);
            }
        }
        __syncwarp();
    }

    // ---- epilogue ----
    float inv0 = 1.0f / l0, inv1 = 1.0f / l1;
    float* Og = &g_O[((size_t)(b * NH + h) * NS + qt * 128) * ND];
    #pragma unroll
    for (int nb = 0; nb < 16; nb++) {
        int c = nb * 8 + 2 * lc;
        *(float2*)&Og[(size_t)(wid * 16 + lg) * ND + c] =
            make_float2(oacc[nb][0] * inv0, oacc[nb][1] * inv0);
        *(float2*)&Og[(size_t)(wid * 16 + lg + 8) * ND + c] =
            make_float2(oacc[nb][2] * inv1, oacc[nb][3] * inv1);
    }
}

// ---------------------------------------------------------------------------
// Kernel 3a: zero output
// ---------------------------------------------------------------------------
__global__ void zero_kernel(float* __restrict__ out, int n) {
    int i = blockIdx.x * 256 + threadIdx.x;
    if (i * 4 < n) *(float4*)&out[i * 4] = make_float4(0.f, 0.f, 0.f, 0.f);
}

// ---------------------------------------------------------------------------
// Kernel 3b: output projection, split-K x4 with atomicAdd.
// ---------------------------------------------------------------------------
__global__ __launch_bounds__(256) void out_kernel(
    const float* __restrict__ Wo, float* __restrict__ out)
{
    __shared__ float At[32 * 64];
    __shared__ float Bs[32 * 64];

    int row0 = blockIdx.y * 64, col0 = blockIdx.x * 64;
    int kz0 = blockIdx.z * (NINNER / 4);
    int tid = threadIdx.x, ty = tid / 16, tx = tid % 16;
    float acc[4][4] = {};

    for (int k0 = kz0; k0 < kz0 + NINNER / 4; k0 += 32) {
        __syncthreads();
        for (int i = tid * 4; i < 64 * 32; i += 1024) {
            int r = i >> 5, k = i & 31;
            int row = row0 + r;
            int b = row >> 11, s = row & (NS - 1);
            int kk = k0 + k;
            int h = kk >> 7, d = kk & 127;
            float4 v = *(const float4*)&g_O[((size_t)(b * NH + h) * NS + s) * ND + d];
            At[(k + 0) * 64 + r] = v.x;
            At[(k + 1) * 64 + r] = v.y;
            At[(k + 2) * 64 + r] = v.z;
            At[(k + 3) * 64 + r] = v.w;
        }
        for (int i = tid * 4; i < 32 * 64; i += 1024) {
            int k = i >> 6, c = i & 63;
            *(float4*)&Bs[k * 64 + c] = *(const float4*)&Wo[(size_t)(k0 + k) * NE + col0 + c];
        }
        __syncthreads();
        #pragma unroll
        for (int k = 0; k < 32; k++) {
            float4 av = *(float4*)&At[k * 64 + ty * 4];
            float4 bv = *(float4*)&Bs[k * 64 + tx * 4];
            float a[4] = {av.x, av.y, av.z, av.w};
            float bb[4] = {bv.x, bv.y, bv.z, bv.w};
            #pragma unroll
            for (int j = 0; j < 4; j++)
                #pragma unroll
                for (int i = 0; i < 4; i++)
                    acc[j][i] += a[j] * bb[i];
        }
    }

    #pragma unroll
    for (int j = 0; j < 4; j++) {
        int row = row0 + ty * 4 + j;
        #pragma unroll
        for (int i = 0; i < 4; i++)
            atomicAdd(&out[(size_t)row * NE + col0 + tx * 4 + i], acc[j][i]);
    }
}

// ---------------------------------------------------------------------------
extern "C" void kernel_launch(void* const* d_in, const int* in_sizes, int n_in,
                              void* d_out, int out_size) {
    const float* q  = (const float*)d_in[0];
    const float* Wq = (const float*)d_in[1];
    const float* Wk = (const float*)d_in[2];
    const float* Wv = (const float*)d_in[3];
    const float* Wo = (const float*)d_in[4];
    float* out = (float*)d_out;

    cudaFuncSetAttribute(proj_kernel, cudaFuncAttributeMaxDynamicSharedMemorySize, 65536);
    cudaFuncSetAttribute(attn_kernel, cudaFuncAttributeMaxDynamicSharedMemorySize, ATTN_SMEM);

    rope_table_kernel<<<(NS * HALF + 255) / 256, 256>>>();

    dim3 g1(NINNER / 64, NROWS / 64, 3);
    proj_kernel<<<g1, 256, 65536>>>(q, Wq, Wk, Wv);

    dim3 g2(NS / 128, NH, NB);
    attn_kernel<<<g2, 256, ATTN_SMEM>>>();

    zero_kernel<<<(NROWS * NE / 4 + 255) / 256, 256>>>(out, NROWS * NE);

    dim3 g3(NE / 64, NROWS / 64, 4);
    out_kernel<<<g3, 256>>>(Wo, out);
}

// round 6
// speedup vs baseline: 4.0883x; 1.4415x over previous
#include <cuda_runtime.h>
#include <math.h>
#include <stdint.h>

#define NB 2
#define NS 2048
#define NE 128
#define NH 16
#define ND 128
#define NINNER 2048
#define NROWS 4096
#define HALF 64

// Scratch
__device__ float  g_Q[NB*NH*NS*ND];
__device__ float  g_K[NB*NH*NS*ND];
__device__ float  g_V[NB*NH*NS*ND];
__device__ float  g_O[NB*NH*NS*ND];
__device__ float2 g_rope[NS*HALF];

// ---------------------------------------------------------------------------
__global__ void rope_table_kernel() {
    int idx = blockIdx.x * 256 + threadIdx.x;
    if (idx >= NS * HALF) return;
    int s = idx / HALF, p = idx % HALF;
    double inv = exp(-(double)p * (log(10000.0) / 64.0));
    double a = (double)s * inv;
    g_rope[idx] = make_float2((float)cos(a), (float)sin(a));
}

// ---------------------------------------------------------------------------
// helpers
// ---------------------------------------------------------------------------
__device__ __forceinline__ uint32_t f2tf(float f) {
    uint32_t u;
    asm("cvt.rna.tf32.f32 %0, %1;" : "=r"(u) : "f"(f));
    return u;
}
__device__ __forceinline__ float f2tf_f(float f) {
    return __uint_as_float(f2tf(f));
}
__device__ __forceinline__ void mma8(float* c, uint32_t a0, uint32_t a1,
                                     uint32_t a2, uint32_t a3,
                                     uint32_t b0, uint32_t b1) {
    asm("mma.sync.aligned.m16n8k8.row.col.f32.tf32.tf32.f32 "
        "{%0,%1,%2,%3},{%4,%5,%6,%7},{%8,%9},{%0,%1,%2,%3};"
        : "+f"(c[0]), "+f"(c[1]), "+f"(c[2]), "+f"(c[3])
        : "r"(a0), "r"(a1), "r"(a2), "r"(a3), "r"(b0), "r"(b1));
}
__device__ __forceinline__ float ex2(float x) {
    float y;
    asm("ex2.approx.f32 %0, %1;" : "=f"(y) : "f"(x));
    return y;
}
__device__ __forceinline__ void cp16(uint32_t dst, const void* src) {
    asm volatile("cp.async.cg.shared.global [%0], [%1], 16;"
                 :: "r"(dst), "l"(src));
}
__device__ __forceinline__ void cp_commit() {
    asm volatile("cp.async.commit_group;");
}
template <int N>
__device__ __forceinline__ void cp_wait() {
    asm volatile("cp.async.wait_group %0;" :: "n"(N));
}

// ---------------------------------------------------------------------------
// Kernel 1: fused QKV projection, tf32 tensor cores + RoPE epilogue.
// Tile 128x128, K=128 (one pass). 256 thr / 8 warps; warp = 16-row stripe.
// Outputs are written ALREADY tf32-rounded (and Q pre-scaled by scale*log2e)
// so the attention kernel can copy them raw via cp.async.
// ---------------------------------------------------------------------------
#define PROJ_SMEM (2 * 128 * 132 * 4)

__global__ __launch_bounds__(256, 1) void proj_kernel(
    const float* __restrict__ q, const float* __restrict__ Wq,
    const float* __restrict__ Wk, const float* __restrict__ Wv)
{
    extern __shared__ float sm[];
    float* At = sm;              // [128][132]   A rows (tf32)
    float* Bs = sm + 128 * 132;  // [128][132]   W rows (tf32), [k][c]

    int z = blockIdx.z;
    const float* W = (z == 0) ? Wq : (z == 1) ? Wk : Wv;
    float* dst = (z == 0) ? g_Q : (z == 1) ? g_K : g_V;

    int h = blockIdx.x;              // col tile == head (128 cols)
    int row0 = blockIdx.y * 128;
    int col0 = h * 128;
    int tid = threadIdx.x;
    int wid = tid >> 5, lane = tid & 31;
    int lg = lane >> 2, lc = lane & 3;

    for (int i = tid * 4; i < 128 * 128; i += 1024) {
        int r = i >> 7, k = i & 127;
        float4 v = *(const float4*)&q[(size_t)(row0 + r) * NE + k];
        *(float4*)&At[r * 132 + k] =
            make_float4(f2tf_f(v.x), f2tf_f(v.y), f2tf_f(v.z), f2tf_f(v.w));
        float4 w = *(const float4*)&W[(size_t)(i >> 7) * NINNER + col0 + (i & 127)];
        *(float4*)&Bs[(i >> 7) * 132 + (i & 127)] =
            make_float4(f2tf_f(w.x), f2tf_f(w.y), f2tf_f(w.z), f2tf_f(w.w));
    }
    __syncthreads();

    float acc[16][4] = {};
    #pragma unroll
    for (int ks = 0; ks < 16; ks++) {
        const float* arow = &At[(wid * 16 + lg) * 132 + ks * 8 + lc];
        uint32_t a0 = __float_as_uint(arow[0]);
        uint32_t a1 = __float_as_uint(arow[8 * 132]);
        uint32_t a2 = __float_as_uint(arow[4]);
        uint32_t a3 = __float_as_uint(arow[8 * 132 + 4]);
        #pragma unroll
        for (int nb = 0; nb < 16; nb++) {
            const float* brow = &Bs[(ks * 8 + lc) * 132 + nb * 8 + lg];
            uint32_t b0 = __float_as_uint(brow[0]);
            uint32_t b1 = __float_as_uint(brow[4 * 132]);
            mma8(acc[nb], a0, a1, a2, a3, b0, b1);
        }
    }

    // Epilogue: RoPE (Q,K), tf32 rounding, Q pre-scale; write [B,H,S,D].
    const float qscale = 0.08838834764831845f * 1.4426950408889634f;
    float oscale = (z == 0) ? qscale : 1.0f;
    bool do_rope = (z < 2);

    int row_a = row0 + wid * 16 + lg;
    int b = row_a >> 11;
    int s0 = row_a & (NS - 1);
    int s1 = s0 + 8;
    float* d0p = &dst[((size_t)(b * NH + h) * NS + s0) * ND];
    float* d1p = &dst[((size_t)(b * NH + h) * NS + s1) * ND];

    #pragma unroll
    for (int nb = 0; nb < 16; nb++) {
        int dcol = nb * 8 + 2 * lc;
        int p = nb * 4 + lc;
        float c0 = acc[nb][0], c1 = acc[nb][1];
        float c2 = acc[nb][2], c3 = acc[nb][3];
        if (do_rope) {
            float2 csa = g_rope[s0 * HALF + p];
            float2 csb = g_rope[s1 * HALF + p];
            float r0 = c0 * csa.x - c1 * csa.y;
            float r1 = c1 * csa.x + c0 * csa.y;
            float r2 = c2 * csb.x - c3 * csb.y;
            float r3 = c3 * csb.x + c2 * csb.y;
            c0 = r0; c1 = r1; c2 = r2; c3 = r3;
        }
        *(float2*)&d0p[dcol] = make_float2(f2tf_f(c0 * oscale), f2tf_f(c1 * oscale));
        *(float2*)&d1p[dcol] = make_float2(f2tf_f(c2 * oscale), f2tf_f(c3 * oscale));
    }
}

// ---------------------------------------------------------------------------
// Kernel 2: causal flash attention, tf32 mma + cp.async pipeline.
// Qs [128][132]; Ks double-buffered [2][64][132]; Vs [64][136]; Pt [128][68].
// V(kt) copy overlaps S-compute; K(kt+1) copy overlaps S+PV compute.
// ---------------------------------------------------------------------------
#define QS_OFF 0
#define KS_OFF (128*132)
#define KS_BUF (64*132)
#define VS_OFF (KS_OFF + 2*KS_BUF)
#define PT_OFF (VS_OFF + 64*136)
#define ATTN_SMEM ((PT_OFF + 128*68) * 4)

__global__ __launch_bounds__(256, 1) void attn_kernel() {
    extern __shared__ float sm[];
    float* Qs = sm + QS_OFF;
    float* Vs = sm + VS_OFF;
    float* Pt = sm + PT_OFF;

    uint32_t smem_u32 = (uint32_t)__cvta_generic_to_shared(sm);
    uint32_t ks_u32[2] = { smem_u32 + KS_OFF * 4, smem_u32 + (KS_OFF + KS_BUF) * 4 };
    uint32_t vs_u32 = smem_u32 + VS_OFF * 4;

    int qt = gridDim.x - 1 - blockIdx.x;   // heavy tiles first
    int h = blockIdx.y, b = blockIdx.z;
    const float* Qg = &g_Q[((size_t)(b * NH + h) * NS + qt * 128) * ND];
    const float* Kg = &g_K[(size_t)(b * NH + h) * NS * ND];
    const float* Vg = &g_V[(size_t)(b * NH + h) * NS * ND];

    int tid = threadIdx.x;
    int wid = tid >> 5, lane = tid & 31;
    int lg = lane >> 2, lc = lane & 3;

    int nkt = 2 * qt + 2;

    // Prologue: kick off K(0) copy, then stage Q (plain copy; pre-rounded).
    {
        const char* src = (const char*)(Kg);
        #pragma unroll
        for (int j = 0; j < 8; j++) {
            int c = tid + j * 256;
            int r = c >> 5, off = (c & 31) << 4;
            cp16(ks_u32[0] + r * 528 + off, src + r * 512 + off);
        }
        cp_commit();
    }
    for (int i = tid * 4; i < 128 * 128; i += 1024) {
        int r = i >> 7, c = i & 127;
        *(float4*)&Qs[r * 132 + c] = *(const float4*)&Qg[(size_t)r * ND + c];
    }

    float oacc[16][4] = {};
    float m0 = -1e30f, m1 = -1e30f, l0 = 0.0f, l1 = 0.0f;

    int row_g0 = qt * 128 + wid * 16 + lg;
    int row_g1 = row_g0 + 8;

    for (int kt = 0; kt < nkt; kt++) {
        cp_wait<0>();          // K(kt) resident
        __syncthreads();       // visible to all; Vs/Ks[nxt] free

        // issue V(kt) copy (overlaps S)
        {
            const char* src = (const char*)(Vg + (size_t)kt * 64 * ND);
            #pragma unroll
            for (int j = 0; j < 8; j++) {
                int c = tid + j * 256;
                int r = c >> 5, off = (c & 31) << 4;
                cp16(vs_u32 + r * 544 + off, src + r * 512 + off);
            }
            cp_commit();
        }
        // issue K(kt+1) copy (overlaps S+PV)
        if (kt + 1 < nkt) {
            const char* src = (const char*)(Kg + (size_t)(kt + 1) * 64 * ND);
            uint32_t dstb = ks_u32[(kt + 1) & 1];
            #pragma unroll
            for (int j = 0; j < 8; j++) {
                int c = tid + j * 256;
                int r = c >> 5, off = (c & 31) << 4;
                cp16(dstb + r * 528 + off, src + r * 512 + off);
            }
            cp_commit();
        }

        const float* Ks = sm + KS_OFF + (kt & 1) * KS_BUF;

        // ---- S = Q @ K^T ----
        float sacc[8][4] = {};
        #pragma unroll
        for (int ks = 0; ks < 16; ks++) {
            const float* qrow = &Qs[(wid * 16 + lg) * 132 + ks * 8 + lc];
            uint32_t a0 = __float_as_uint(qrow[0]);
            uint32_t a1 = __float_as_uint(qrow[8 * 132]);
            uint32_t a2 = __float_as_uint(qrow[4]);
            uint32_t a3 = __float_as_uint(qrow[8 * 132 + 4]);
            #pragma unroll
            for (int nb = 0; nb < 8; nb++) {
                const float* krow = &Ks[(nb * 8 + lg) * 132 + ks * 8 + lc];
                uint32_t b0 = __float_as_uint(krow[0]);
                uint32_t b1 = __float_as_uint(krow[4]);
                mma8(sacc[nb], a0, a1, a2, a3, b0, b1);
            }
        }

        // ---- causal mask ----
        if (kt >= 2 * qt) {
            #pragma unroll
            for (int nb = 0; nb < 8; nb++) {
                int col_g = kt * 64 + nb * 8 + 2 * lc;
                if (col_g     > row_g0) sacc[nb][0] = -1e30f;
                if (col_g + 1 > row_g0) sacc[nb][1] = -1e30f;
                if (col_g     > row_g1) sacc[nb][2] = -1e30f;
                if (col_g + 1 > row_g1) sacc[nb][3] = -1e30f;
            }
        }

        // ---- online softmax (log2 domain) ----
        float mt0 = -1e30f, mt1 = -1e30f;
        #pragma unroll
        for (int nb = 0; nb < 8; nb++) {
            mt0 = fmaxf(mt0, fmaxf(sacc[nb][0], sacc[nb][1]));
            mt1 = fmaxf(mt1, fmaxf(sacc[nb][2], sacc[nb][3]));
        }
        mt0 = fmaxf(mt0, __shfl_xor_sync(0xFFFFFFFFu, mt0, 1));
        mt0 = fmaxf(mt0, __shfl_xor_sync(0xFFFFFFFFu, mt0, 2));
        mt1 = fmaxf(mt1, __shfl_xor_sync(0xFFFFFFFFu, mt1, 1));
        mt1 = fmaxf(mt1, __shfl_xor_sync(0xFFFFFFFFu, mt1, 2));
        float mn0 = fmaxf(m0, mt0), mn1 = fmaxf(m1, mt1);
        float al0 = ex2(m0 - mn0), al1 = ex2(m1 - mn1);
        m0 = mn0; m1 = mn1;

        float r0 = 0.0f, r1 = 0.0f;
        #pragma unroll
        for (int nb = 0; nb < 8; nb++) {
            float p0 = ex2(sacc[nb][0] - mn0);
            float p1 = ex2(sacc[nb][1] - mn0);
            float p2 = ex2(sacc[nb][2] - mn1);
            float p3 = ex2(sacc[nb][3] - mn1);
            r0 += p0 + p1; r1 += p2 + p3;
            *(float2*)&Pt[(wid * 16 + lg) * 68 + nb * 8 + 2 * lc] = make_float2(p0, p1);
            *(float2*)&Pt[(wid * 16 + lg + 8) * 68 + nb * 8 + 2 * lc] = make_float2(p2, p3);
        }
        r0 += __shfl_xor_sync(0xFFFFFFFFu, r0, 1);
        r0 += __shfl_xor_sync(0xFFFFFFFFu, r0, 2);
        r1 += __shfl_xor_sync(0xFFFFFFFFu, r1, 1);
        r1 += __shfl_xor_sync(0xFFFFFFFFu, r1, 2);
        l0 = l0 * al0 + r0;
        l1 = l1 * al1 + r1;

        #pragma unroll
        for (int nb = 0; nb < 16; nb++) {
            oacc[nb][0] *= al0; oacc[nb][1] *= al0;
            oacc[nb][2] *= al1; oacc[nb][3] *= al1;
        }
        __syncwarp();

        // V(kt) must be resident for everyone
        if (kt + 1 < nkt) cp_wait<1>(); else cp_wait<0>();
        __syncthreads();

        // ---- O += P @ V ----
        #pragma unroll
        for (int ks = 0; ks < 8; ks++) {
            const float* prow = &Pt[(wid * 16 + lg) * 68 + ks * 8 + lc];
            uint32_t a0 = __float_as_uint(prow[0]);
            uint32_t a1 = __float_as_uint(prow[8 * 68]);
            uint32_t a2 = __float_as_uint(prow[4]);
            uint32_t a3 = __float_as_uint(prow[8 * 68 + 4]);
            #pragma unroll
            for (int nb = 0; nb < 16; nb++) {
                const float* vrow = &Vs[(ks * 8 + lc) * 136 + nb * 8 + lg];
                uint32_t b0 = __float_as_uint(vrow[0]);
                uint32_t b1 = __float_as_uint(vrow[4 * 136]);
                mma8(oacc[nb], a0, a1, a2, a3, b0, b1);
            }
        }
    }

    // ---- epilogue ----
    float inv0 = 1.0f / l0, inv1 = 1.0f / l1;
    float* Og = &g_O[((size_t)(b * NH + h) * NS + qt * 128) * ND];
    #pragma unroll
    for (int nb = 0; nb < 16; nb++) {
        int c = nb * 8 + 2 * lc;
        *(float2*)&Og[(size_t)(wid * 16 + lg) * ND + c] =
            make_float2(oacc[nb][0] * inv0, oacc[nb][1] * inv0);
        *(float2*)&Og[(size_t)(wid * 16 + lg + 8) * ND + c] =
            make_float2(oacc[nb][2] * inv1, oacc[nb][3] * inv1);
    }
}

// ---------------------------------------------------------------------------
__global__ void zero_kernel(float* __restrict__ out, int n) {
    int i = blockIdx.x * 256 + threadIdx.x;
    if (i * 4 < n) *(float4*)&out[i * 4] = make_float4(0.f, 0.f, 0.f, 0.f);
}

// ---------------------------------------------------------------------------
// Kernel 3: output projection, fp32, split-K x4 with atomicAdd.
// ---------------------------------------------------------------------------
__global__ __launch_bounds__(256) void out_kernel(
    const float* __restrict__ Wo, float* __restrict__ out)
{
    __shared__ float At[32 * 64];
    __shared__ float Bs[32 * 64];

    int row0 = blockIdx.y * 64, col0 = blockIdx.x * 64;
    int kz0 = blockIdx.z * (NINNER / 4);
    int tid = threadIdx.x, ty = tid / 16, tx = tid % 16;
    float acc[4][4] = {};

    for (int k0 = kz0; k0 < kz0 + NINNER / 4; k0 += 32) {
        __syncthreads();
        for (int i = tid * 4; i < 64 * 32; i += 1024) {
            int r = i >> 5, k = i & 31;
            int row = row0 + r;
            int b = row >> 11, s = row & (NS - 1);
            int kk = k0 + k;
            int h = kk >> 7, d = kk & 127;
            float4 v = *(const float4*)&g_O[((size_t)(b * NH + h) * NS + s) * ND + d];
            At[(k + 0) * 64 + r] = v.x;
            At[(k + 1) * 64 + r] = v.y;
            At[(k + 2) * 64 + r] = v.z;
            At[(k + 3) * 64 + r] = v.w;
        }
        for (int i = tid * 4; i < 32 * 64; i += 1024) {
            int k = i >> 6, c = i & 63;
            *(float4*)&Bs[k * 64 + c] = *(const float4*)&Wo[(size_t)(k0 + k) * NE + col0 + c];
        }
        __syncthreads();
        #pragma unroll
        for (int k = 0; k < 32; k++) {
            float4 av = *(float4*)&At[k * 64 + ty * 4];
            float4 bv = *(float4*)&Bs[k * 64 + tx * 4];
            float a[4] = {av.x, av.y, av.z, av.w};
            float bb[4] = {bv.x, bv.y, bv.z, bv.w};
            #pragma unroll
            for (int j = 0; j < 4; j++)
                #pragma unroll
                for (int i = 0; i < 4; i++)
                    acc[j][i] += a[j] * bb[i];
        }
    }

    #pragma unroll
    for (int j = 0; j < 4; j++) {
        int row = row0 + ty * 4 + j;
        #pragma unroll
        for (int i = 0; i < 4; i++)
            atomicAdd(&out[(size_t)row * NE + col0 + tx * 4 + i], acc[j][i]);
    }
}

// ---------------------------------------------------------------------------
extern "C" void kernel_launch(void* const* d_in, const int* in_sizes, int n_in,
                              void* d_out, int out_size) {
    const float* q  = (const float*)d_in[0];
    const float* Wq = (const float*)d_in[1];
    const float* Wk = (const float*)d_in[2];
    const float* Wv = (const float*)d_in[3];
    const float* Wo = (const float*)d_in[4];
    float* out = (float*)d_out;

    cudaFuncSetAttribute(proj_kernel, cudaFuncAttributeMaxDynamicSharedMemorySize, PROJ_SMEM);
    cudaFuncSetAttribute(attn_kernel, cudaFuncAttributeMaxDynamicSharedMemorySize, ATTN_SMEM);

    rope_table_kernel<<<(NS * HALF + 255) / 256, 256>>>();

    dim3 g1(NINNER / 128, NROWS / 128, 3);
    proj_kernel<<<g1, 256, PROJ_SMEM>>>(q, Wq, Wk, Wv);

    dim3 g2(NS / 128, NH, NB);
    attn_kernel<<<g2, 256, ATTN_SMEM>>>();

    zero_kernel<<<(NROWS * NE / 4 + 255) / 256, 256>>>(out, NROWS * NE);

    dim3 g3(NE / 64, NROWS / 64, 4);
    out_kernel<<<g3, 256>>>(Wo, out);
}

// round 8
// speedup vs baseline: 6.0938x; 1.4906x over previous
#include <cuda_runtime.h>
#include <cuda_fp16.h>
#include <math.h>
#include <stdint.h>

#define NB 2
#define NS 2048
#define NE 128
#define NH 16
#define ND 128
#define NINNER 2048
#define NROWS 4096
#define HALF 64

// Scratch
__device__ __half g_Qh[NB*NH*NS*ND];
__device__ __half g_Kh[NB*NH*NS*ND];
__device__ __half g_Vh[NB*NH*NS*ND];
__device__ float  g_O[NB*NH*NS*ND];
__device__ float2 g_rope[NS*HALF];

// ---------------------------------------------------------------------------
__global__ void rope_table_kernel() {
    int idx = blockIdx.x * 256 + threadIdx.x;
    if (idx >= NS * HALF) return;
    int s = idx / HALF, p = idx % HALF;
    double inv = exp(-(double)p * (log(10000.0) / 64.0));
    double a = (double)s * inv;
    g_rope[idx] = make_float2((float)cos(a), (float)sin(a));
}

// ---------------------------------------------------------------------------
// helpers
// ---------------------------------------------------------------------------
__device__ __forceinline__ uint32_t f2tf(float f) {
    uint32_t u;
    asm("cvt.rna.tf32.f32 %0, %1;" : "=r"(u) : "f"(f));
    return u;
}
__device__ __forceinline__ float f2tf_f(float f) {
    return __uint_as_float(f2tf(f));
}
__device__ __forceinline__ void mma8(float* c, uint32_t a0, uint32_t a1,
                                     uint32_t a2, uint32_t a3,
                                     uint32_t b0, uint32_t b1) {
    asm("mma.sync.aligned.m16n8k8.row.col.f32.tf32.tf32.f32 "
        "{%0,%1,%2,%3},{%4,%5,%6,%7},{%8,%9},{%0,%1,%2,%3};"
        : "+f"(c[0]), "+f"(c[1]), "+f"(c[2]), "+f"(c[3])
        : "r"(a0), "r"(a1), "r"(a2), "r"(a3), "r"(b0), "r"(b1));
}
__device__ __forceinline__ void mma16(float* c, uint32_t a0, uint32_t a1,
                                      uint32_t a2, uint32_t a3,
                                      uint32_t b0, uint32_t b1) {
    asm("mma.sync.aligned.m16n8k16.row.col.f32.f16.f16.f32 "
        "{%0,%1,%2,%3},{%4,%5,%6,%7},{%8,%9},{%0,%1,%2,%3};"
        : "+f"(c[0]), "+f"(c[1]), "+f"(c[2]), "+f"(c[3])
        : "r"(a0), "r"(a1), "r"(a2), "r"(a3), "r"(b0), "r"(b1));
}
__device__ __forceinline__ void ldsm_x4(uint32_t* r, uint32_t addr) {
    asm volatile("ldmatrix.sync.aligned.m8n8.x4.shared.b16 {%0,%1,%2,%3}, [%4];"
        : "=r"(r[0]), "=r"(r[1]), "=r"(r[2]), "=r"(r[3]) : "r"(addr));
}
__device__ __forceinline__ void ldsm_x4t(uint32_t* r, uint32_t addr) {
    asm volatile("ldmatrix.sync.aligned.m8n8.x4.trans.shared.b16 {%0,%1,%2,%3}, [%4];"
        : "=r"(r[0]), "=r"(r[1]), "=r"(r[2]), "=r"(r[3]) : "r"(addr));
}
__device__ __forceinline__ float ex2(float x) {
    float y;
    asm("ex2.approx.f32 %0, %1;" : "=f"(y) : "f"(x));
    return y;
}
__device__ __forceinline__ uint32_t pack2(float a, float b) {
    __half2 h = __floats2half2_rn(a, b);
    return *(uint32_t*)&h;
}
__device__ __forceinline__ void cp16(uint32_t dst, const void* src) {
    asm volatile("cp.async.cg.shared.global [%0], [%1], 16;"
                 :: "r"(dst), "l"(src));
}
__device__ __forceinline__ void cp_commit() {
    asm volatile("cp.async.commit_group;");
}
template <int N>
__device__ __forceinline__ void cp_wait() {
    asm volatile("cp.async.wait_group %0;" :: "n"(N));
}

// ---------------------------------------------------------------------------
// Kernel 1: fused QKV projection, tf32 mma + RoPE epilogue, __half output.
// Q output pre-scaled by (1/sqrt(128))*log2(e).
// ---------------------------------------------------------------------------
#define PROJ_SMEM (2 * 128 * 132 * 4)

__global__ __launch_bounds__(256, 1) void proj_kernel(
    const float* __restrict__ q, const float* __restrict__ Wq,
    const float* __restrict__ Wk, const float* __restrict__ Wv)
{
    extern __shared__ float sm[];
    float* At = sm;              // [128][132]
    float* Bs = sm + 128 * 132;  // [128][132]

    int z = blockIdx.z;
    const float* W = (z == 0) ? Wq : (z == 1) ? Wk : Wv;
    __half* dst = (z == 0) ? g_Qh : (z == 1) ? g_Kh : g_Vh;

    int h = blockIdx.x;
    int row0 = blockIdx.y * 128;
    int col0 = h * 128;
    int tid = threadIdx.x;
    int wid = tid >> 5, lane = tid & 31;
    int lg = lane >> 2, lc = lane & 3;

    for (int i = tid * 4; i < 128 * 128; i += 1024) {
        int r = i >> 7, k = i & 127;
        float4 v = *(const float4*)&q[(size_t)(row0 + r) * NE + k];
        *(float4*)&At[r * 132 + k] =
            make_float4(f2tf_f(v.x), f2tf_f(v.y), f2tf_f(v.z), f2tf_f(v.w));
        float4 w = *(const float4*)&W[(size_t)r * NINNER + col0 + k];
        *(float4*)&Bs[r * 132 + k] =
            make_float4(f2tf_f(w.x), f2tf_f(w.y), f2tf_f(w.z), f2tf_f(w.w));
    }
    __syncthreads();

    float acc[16][4] = {};
    #pragma unroll
    for (int ks = 0; ks < 16; ks++) {
        const float* arow = &At[(wid * 16 + lg) * 132 + ks * 8 + lc];
        uint32_t a0 = __float_as_uint(arow[0]);
        uint32_t a1 = __float_as_uint(arow[8 * 132]);
        uint32_t a2 = __float_as_uint(arow[4]);
        uint32_t a3 = __float_as_uint(arow[8 * 132 + 4]);
        #pragma unroll
        for (int nb = 0; nb < 16; nb++) {
            const float* brow = &Bs[(ks * 8 + lc) * 132 + nb * 8 + lg];
            uint32_t b0 = __float_as_uint(brow[0]);
            uint32_t b1 = __float_as_uint(brow[4 * 132]);
            mma8(acc[nb], a0, a1, a2, a3, b0, b1);
        }
    }

    const float qscale = 0.08838834764831845f * 1.4426950408889634f;
    float oscale = (z == 0) ? qscale : 1.0f;
    bool do_rope = (z < 2);

    int row_a = row0 + wid * 16 + lg;
    int b = row_a >> 11;
    int s0 = row_a & (NS - 1);
    int s1 = s0 + 8;
    __half* d0p = &dst[((size_t)(b * NH + h) * NS + s0) * ND];
    __half* d1p = &dst[((size_t)(b * NH + h) * NS + s1) * ND];

    #pragma unroll
    for (int nb = 0; nb < 16; nb++) {
        int dcol = nb * 8 + 2 * lc;
        int p = nb * 4 + lc;
        float c0 = acc[nb][0], c1 = acc[nb][1];
        float c2 = acc[nb][2], c3 = acc[nb][3];
        if (do_rope) {
            float2 csa = g_rope[s0 * HALF + p];
            float2 csb = g_rope[s1 * HALF + p];
            float r0 = c0 * csa.x - c1 * csa.y;
            float r1 = c1 * csa.x + c0 * csa.y;
            float r2 = c2 * csb.x - c3 * csb.y;
            float r3 = c3 * csb.x + c2 * csb.y;
            c0 = r0; c1 = r1; c2 = r2; c3 = r3;
        }
        *(uint32_t*)&d0p[dcol] = pack2(c0 * oscale, c1 * oscale);
        *(uint32_t*)&d1p[dcol] = pack2(c2 * oscale, c3 * oscale);
    }
}

// ---------------------------------------------------------------------------
// Kernel 2: causal flash attention, fp16 mma (fp32 accum), cp.async pipeline.
// smem (bytes, pitch 272): Ks[2][64], Vs[2][64], Qstage[128]. 104448 B.
// Q fragments in registers; P reused from S C-fragments (no smem P).
// ---------------------------------------------------------------------------
#define PITCHB 272
#define KS_SZ  (64 * PITCHB)
#define KS_OFF 0
#define VS_OFF (2 * KS_SZ)
#define QST_OFF (4 * KS_SZ)
#define ATTN_SMEM (QST_OFF + 128 * PITCHB)

__global__ __launch_bounds__(256, 1) void attn_kernel() {
    extern __shared__ char smem[];
    uint32_t sbase = (uint32_t)__cvta_generic_to_shared(smem);

    int qt = gridDim.x - 1 - blockIdx.x;   // heavy tiles first
    int h = blockIdx.y, b = blockIdx.z;
    const __half* Qg = &g_Qh[((size_t)(b * NH + h) * NS + qt * 128) * ND];
    const __half* Kg = &g_Kh[(size_t)(b * NH + h) * NS * ND];
    const __half* Vg = &g_Vh[(size_t)(b * NH + h) * NS * ND];

    int tid = threadIdx.x;
    int wid = tid >> 5, lane = tid & 31;
    int lg = lane >> 2, lc = lane & 3;

    int nkt = 2 * qt + 2;

    // group0: K(0), V(0)
    {
        const char* sk = (const char*)Kg;
        const char* sv = (const char*)Vg;
        #pragma unroll
        for (int j = 0; j < 4; j++) {
            int idx = tid + j * 256;
            int r = idx >> 4, c = (idx & 15) << 4;
            cp16(sbase + KS_OFF + r * PITCHB + c, sk + r * 256 + c);
            cp16(sbase + VS_OFF + r * PITCHB + c, sv + r * 256 + c);
        }
        cp_commit();
    }
    // stage Q (plain 16B copies)
    #pragma unroll
    for (int j = 0; j < 8; j++) {
        int idx = tid + j * 256;
        int r = idx >> 4, c = (idx & 15) << 4;
        *(uint4*)(smem + QST_OFF + r * PITCHB + c) =
            *(const uint4*)((const char*)Qg + r * 256 + c);
    }
    __syncthreads();

    // lane offsets for ldmatrix tile addressing
    uint32_t laneQ = ((lane & 7) + ((lane >> 3) & 1) * 8) * PITCHB + ((lane >> 4) & 1) * 16;
    uint32_t laneK = ((lane & 7) + ((lane >> 4) & 1) * 8) * PITCHB + ((lane >> 3) & 1) * 16;
    uint32_t laneV = laneQ;   // same pattern as Q

    // Q fragments -> registers (once)
    uint32_t qa[8][4];
    {
        uint32_t qaddr = sbase + QST_OFF + wid * 16 * PITCHB + laneQ;
        #pragma unroll
        for (int kg = 0; kg < 8; kg++) ldsm_x4(qa[kg], qaddr + kg * 32);
    }

    float oacc[16][4] = {};
    float m0 = -1e30f, m1 = -1e30f, l0 = 0.0f, l1 = 0.0f;
    int row_g0 = qt * 128 + wid * 16 + lg;
    int row_g1 = row_g0 + 8;

    for (int kt = 0; kt < nkt; kt++) {
        cp_wait<0>();          // K(kt), V(kt) resident
        __syncthreads();       // all warps done with (kt-1) buffers

        int buf = kt & 1;
        if (kt + 1 < nkt) {    // prefetch next K,V into other buffers
            const char* sk = (const char*)(Kg + (size_t)(kt + 1) * 64 * ND);
            const char* sv = (const char*)(Vg + (size_t)(kt + 1) * 64 * ND);
            uint32_t kd = sbase + KS_OFF + (1 - buf) * KS_SZ;
            uint32_t vd = sbase + VS_OFF + (1 - buf) * KS_SZ;
            #pragma unroll
            for (int j = 0; j < 4; j++) {
                int idx = tid + j * 256;
                int r = idx >> 4, c = (idx & 15) << 4;
                cp16(kd + r * PITCHB + c, sk + r * 256 + c);
                cp16(vd + r * PITCHB + c, sv + r * 256 + c);
            }
            cp_commit();
        }

        // ---- S = Q @ K^T ----
        uint32_t kbase = sbase + KS_OFF + buf * KS_SZ + laneK;
        float sacc[8][4] = {};
        #pragma unroll
        for (int kg = 0; kg < 8; kg++) {
            #pragma unroll
            for (int nbp = 0; nbp < 4; nbp++) {
                uint32_t br[4];
                ldsm_x4(br, kbase + nbp * (16 * PITCHB) + kg * 32);
                mma16(sacc[2 * nbp],     qa[kg][0], qa[kg][1], qa[kg][2], qa[kg][3], br[0], br[1]);
                mma16(sacc[2 * nbp + 1], qa[kg][0], qa[kg][1], qa[kg][2], qa[kg][3], br[2], br[3]);
            }
        }

        // ---- causal mask (only last two K tiles cross the diagonal) ----
        if (kt >= 2 * qt) {
            #pragma unroll
            for (int nb = 0; nb < 8; nb++) {
                int col_g = kt * 64 + nb * 8 + 2 * lc;
                if (col_g     > row_g0) sacc[nb][0] = -1e30f;
                if (col_g + 1 > row_g0) sacc[nb][1] = -1e30f;
                if (col_g     > row_g1) sacc[nb][2] = -1e30f;
                if (col_g + 1 > row_g1) sacc[nb][3] = -1e30f;
            }
        }

        // ---- online softmax (log2 domain) ----
        float mt0 = -1e30f, mt1 = -1e30f;
        #pragma unroll
        for (int nb = 0; nb < 8; nb++) {
            mt0 = fmaxf(mt0, fmaxf(sacc[nb][0], sacc[nb][1]));
            mt1 = fmaxf(mt1, fmaxf(sacc[nb][2], sacc[nb][3]));
        }
        mt0 = fmaxf(mt0, __shfl_xor_sync(0xFFFFFFFFu, mt0, 1));
        mt0 = fmaxf(mt0, __shfl_xor_sync(0xFFFFFFFFu, mt0, 2));
        mt1 = fmaxf(mt1, __shfl_xor_sync(0xFFFFFFFFu, mt1, 1));
        mt1 = fmaxf(mt1, __shfl_xor_sync(0xFFFFFFFFu, mt1, 2));
        float mn0 = fmaxf(m0, mt0), mn1 = fmaxf(m1, mt1);
        float al0 = ex2(m0 - mn0), al1 = ex2(m1 - mn1);
        m0 = mn0; m1 = mn1;

        uint32_t ph[8][2];
        float r0 = 0.0f, r1 = 0.0f;
        #pragma unroll
        for (int nb = 0; nb < 8; nb++) {
            float p0 = ex2(sacc[nb][0] - mn0);
            float p1 = ex2(sacc[nb][1] - mn0);
            float p2 = ex2(sacc[nb][2] - mn1);
            float p3 = ex2(sacc[nb][3] - mn1);
            r0 += p0 + p1; r1 += p2 + p3;
            ph[nb][0] = pack2(p0, p1);   // rows lg
            ph[nb][1] = pack2(p2, p3);   // rows lg+8
        }
        r0 += __shfl_xor_sync(0xFFFFFFFFu, r0, 1);
        r0 += __shfl_xor_sync(0xFFFFFFFFu, r0, 2);
        r1 += __shfl_xor_sync(0xFFFFFFFFu, r1, 1);
        r1 += __shfl_xor_sync(0xFFFFFFFFu, r1, 2);
        l0 = l0 * al0 + r0;
        l1 = l1 * al1 + r1;

        #pragma unroll
        for (int nb = 0; nb < 16; nb++) {
            oacc[nb][0] *= al0; oacc[nb][1] *= al0;
            oacc[nb][2] *= al1; oacc[nb][3] *= al1;
        }

        // ---- O += P @ V (V fragments via ldmatrix.trans) ----
        uint32_t vbase = sbase + VS_OFF + buf * KS_SZ + laneV;
        #pragma unroll
        for (int kg = 0; kg < 4; kg++) {
            uint32_t a0 = ph[2 * kg][0], a1 = ph[2 * kg][1];
            uint32_t a2 = ph[2 * kg + 1][0], a3 = ph[2 * kg + 1][1];
            #pragma unroll
            for (int nbp = 0; nbp < 8; nbp++) {
                uint32_t br[4];
                ldsm_x4t(br, vbase + kg * (16 * PITCHB) + nbp * 32);
                mma16(oacc[2 * nbp],     a0, a1, a2, a3, br[0], br[1]);
                mma16(oacc[2 * nbp + 1], a0, a1, a2, a3, br[2], br[3]);
            }
        }
    }

    // ---- epilogue ----
    float inv0 = 1.0f / l0, inv1 = 1.0f / l1;
    float* Og = &g_O[((size_t)(b * NH + h) * NS + qt * 128) * ND];
    #pragma unroll
    for (int nb = 0; nb < 16; nb++) {
        int c = nb * 8 + 2 * lc;
        *(float2*)&Og[(size_t)(wid * 16 + lg) * ND + c] =
            make_float2(oacc[nb][0] * inv0, oacc[nb][1] * inv0);
        *(float2*)&Og[(size_t)(wid * 16 + lg + 8) * ND + c] =
            make_float2(oacc[nb][2] * inv1, oacc[nb][3] * inv1);
    }
}

// ---------------------------------------------------------------------------
__global__ void zero_kernel(float* __restrict__ out, int n) {
    int i = blockIdx.x * 256 + threadIdx.x;
    if (i * 4 < n) *(float4*)&out[i * 4] = make_float4(0.f, 0.f, 0.f, 0.f);
}

// ---------------------------------------------------------------------------
// Kernel 3: output projection, fp32, split-K x4 with atomicAdd.
// ---------------------------------------------------------------------------
__global__ __launch_bounds__(256) void out_kernel(
    const float* __restrict__ Wo, float* __restrict__ out)
{
    __shared__ float At[32 * 64];
    __shared__ float Bs[32 * 64];

    int row0 = blockIdx.y * 64, col0 = blockIdx.x * 64;
    int kz0 = blockIdx.z * (NINNER / 4);
    int tid = threadIdx.x, ty = tid / 16, tx = tid % 16;
    float acc[4][4] = {};

    for (int k0 = kz0; k0 < kz0 + NINNER / 4; k0 += 32) {
        __syncthreads();
        for (int i = tid * 4; i < 64 * 32; i += 1024) {
            int r = i >> 5, k = i & 31;
            int row = row0 + r;
            int b = row >> 11, s = row & (NS - 1);
            int kk = k0 + k;
            int h = kk >> 7, d = kk & 127;
            float4 v = *(const float4*)&g_O[((size_t)(b * NH + h) * NS + s) * ND + d];
            At[(k + 0) * 64 + r] = v.x;
            At[(k + 1) * 64 + r] = v.y;
            At[(k + 2) * 64 + r] = v.z;
            At[(k + 3) * 64 + r] = v.w;
        }
        for (int i = tid * 4; i < 32 * 64; i += 1024) {
            int k = i >> 6, c = i & 63;
            *(float4*)&Bs[k * 64 + c] = *(const float4*)&Wo[(size_t)(k0 + k) * NE + col0 + c];
        }
        __syncthreads();
        #pragma unroll
        for (int k = 0; k < 32; k++) {
            float4 av = *(float4*)&At[k * 64 + ty * 4];
            float4 bv = *(float4*)&Bs[k * 64 + tx * 4];
            float a[4] = {av.x, av.y, av.z, av.w};
            float bb[4] = {bv.x, bv.y, bv.z, bv.w};
            #pragma unroll
            for (int j = 0; j < 4; j++)
                #pragma unroll
                for (int i = 0; i < 4; i++)
                    acc[j][i] += a[j] * bb[i];
        }
    }

    #pragma unroll
    for (int j = 0; j < 4; j++) {
        int row = row0 + ty * 4 + j;
        #pragma unroll
        for (int i = 0; i < 4; i++)
            atomicAdd(&out[(size_t)row * NE + col0 + tx * 4 + i], acc[j][i]);
    }
}

// ---------------------------------------------------------------------------
extern "C" void kernel_launch(void* const* d_in, const int* in_sizes, int n_in,
                              void* d_out, int out_size) {
    const float* q  = (const float*)d_in[0];
    const float* Wq = (const float*)d_in[1];
    const float* Wk = (const float*)d_in[2];
    const float* Wv = (const float*)d_in[3];
    const float* Wo = (const float*)d_in[4];
    float* out = (float*)d_out;

    cudaFuncSetAttribute(proj_kernel, cudaFuncAttributeMaxDynamicSharedMemorySize, PROJ_SMEM);
    cudaFuncSetAttribute(attn_kernel, cudaFuncAttributeMaxDynamicSharedMemorySize, ATTN_SMEM);

    rope_table_kernel<<<(NS * HALF + 255) / 256, 256>>>();

    dim3 g1(NINNER / 128, NROWS / 128, 3);
    proj_kernel<<<g1, 256, PROJ_SMEM>>>(q, Wq, Wk, Wv);

    dim3 g2(NS / 128, NH, NB);
    attn_kernel<<<g2, 256, ATTN_SMEM>>>();

    zero_kernel<<<(NROWS * NE / 4 + 255) / 256, 256>>>(out, NROWS * NE);

    dim3 g3(NE / 64, NROWS / 64, 4);
    out_kernel<<<g3, 256>>>(Wo, out);
}

// round 9
// speedup vs baseline: 7.5566x; 1.2401x over previous
#include <cuda_runtime.h>
#include <cuda_fp16.h>
#include <math.h>
#include <stdint.h>

#define NB 2
#define NS 2048
#define NE 128
#define NH 16
#define ND 128
#define NINNER 2048
#define NROWS 4096
#define HALF 64

// Scratch
__device__ __half g_Qh[NB*NH*NS*ND];
__device__ __half g_Kh[NB*NH*NS*ND];
__device__ __half g_Vh[NB*NH*NS*ND];
__device__ __half g_Oh[NB*NH*NS*ND];
__device__ __half g_Woh[NINNER*NE];
__device__ float2 g_rope[NS*HALF];

// ---------------------------------------------------------------------------
__global__ void rope_table_kernel() {
    int idx = blockIdx.x * 256 + threadIdx.x;
    if (idx >= NS * HALF) return;
    int s = idx / HALF, p = idx % HALF;
    double inv = exp(-(double)p * (log(10000.0) / 64.0));
    double a = (double)s * inv;
    g_rope[idx] = make_float2((float)cos(a), (float)sin(a));
}

// ---------------------------------------------------------------------------
// helpers
// ---------------------------------------------------------------------------
__device__ __forceinline__ uint32_t f2tf(float f) {
    uint32_t u;
    asm("cvt.rna.tf32.f32 %0, %1;" : "=r"(u) : "f"(f));
    return u;
}
__device__ __forceinline__ float f2tf_f(float f) {
    return __uint_as_float(f2tf(f));
}
__device__ __forceinline__ void mma8(float* c, uint32_t a0, uint32_t a1,
                                     uint32_t a2, uint32_t a3,
                                     uint32_t b0, uint32_t b1) {
    asm("mma.sync.aligned.m16n8k8.row.col.f32.tf32.tf32.f32 "
        "{%0,%1,%2,%3},{%4,%5,%6,%7},{%8,%9},{%0,%1,%2,%3};"
        : "+f"(c[0]), "+f"(c[1]), "+f"(c[2]), "+f"(c[3])
        : "r"(a0), "r"(a1), "r"(a2), "r"(a3), "r"(b0), "r"(b1));
}
__device__ __forceinline__ void mma16(float* c, uint32_t a0, uint32_t a1,
                                      uint32_t a2, uint32_t a3,
                                      uint32_t b0, uint32_t b1) {
    asm("mma.sync.aligned.m16n8k16.row.col.f32.f16.f16.f32 "
        "{%0,%1,%2,%3},{%4,%5,%6,%7},{%8,%9},{%0,%1,%2,%3};"
        : "+f"(c[0]), "+f"(c[1]), "+f"(c[2]), "+f"(c[3])
        : "r"(a0), "r"(a1), "r"(a2), "r"(a3), "r"(b0), "r"(b1));
}
__device__ __forceinline__ void ldsm_x4(uint32_t* r, uint32_t addr) {
    asm volatile("ldmatrix.sync.aligned.m8n8.x4.shared.b16 {%0,%1,%2,%3}, [%4];"
        : "=r"(r[0]), "=r"(r[1]), "=r"(r[2]), "=r"(r[3]) : "r"(addr));
}
__device__ __forceinline__ void ldsm_x4t(uint32_t* r, uint32_t addr) {
    asm volatile("ldmatrix.sync.aligned.m8n8.x4.trans.shared.b16 {%0,%1,%2,%3}, [%4];"
        : "=r"(r[0]), "=r"(r[1]), "=r"(r[2]), "=r"(r[3]) : "r"(addr));
}
__device__ __forceinline__ float ex2(float x) {
    float y;
    asm("ex2.approx.f32 %0, %1;" : "=f"(y) : "f"(x));
    return y;
}
__device__ __forceinline__ uint32_t pack2(float a, float b) {
    __half2 h = __floats2half2_rn(a, b);
    return *(uint32_t*)&h;
}
__device__ __forceinline__ void cp16(uint32_t dst, const void* src) {
    asm volatile("cp.async.cg.shared.global [%0], [%1], 16;"
                 :: "r"(dst), "l"(src));
}
__device__ __forceinline__ void cp_commit() {
    asm volatile("cp.async.commit_group;");
}
template <int N>
__device__ __forceinline__ void cp_wait() {
    asm volatile("cp.async.wait_group %0;" :: "n"(N));
}

// ---------------------------------------------------------------------------
// Kernel 0b: Wo fp32 -> half
// ---------------------------------------------------------------------------
__global__ void wo_half_kernel(const float* __restrict__ Wo) {
    int i = blockIdx.x * 256 + threadIdx.x;      // one float4 per thread
    if (i * 4 >= NINNER * NE) return;
    float4 v = *(const float4*)&Wo[i * 4];
    uint32_t p0 = pack2(v.x, v.y), p1 = pack2(v.z, v.w);
    *(uint2*)&g_Woh[i * 4] = make_uint2(p0, p1);
}

// ---------------------------------------------------------------------------
// Kernel 1: fused QKV projection, tf32 mma + RoPE epilogue, __half output.
// Q output pre-scaled by (1/sqrt(128))*log2(e).
// ---------------------------------------------------------------------------
#define PROJ_SMEM (2 * 128 * 132 * 4)

__global__ __launch_bounds__(256, 1) void proj_kernel(
    const float* __restrict__ q, const float* __restrict__ Wq,
    const float* __restrict__ Wk, const float* __restrict__ Wv)
{
    extern __shared__ float sm[];
    float* At = sm;              // [128][132]
    float* Bs = sm + 128 * 132;  // [128][132]

    int z = blockIdx.z;
    const float* W = (z == 0) ? Wq : (z == 1) ? Wk : Wv;
    __half* dst = (z == 0) ? g_Qh : (z == 1) ? g_Kh : g_Vh;

    int h = blockIdx.x;
    int row0 = blockIdx.y * 128;
    int col0 = h * 128;
    int tid = threadIdx.x;
    int wid = tid >> 5, lane = tid & 31;
    int lg = lane >> 2, lc = lane & 3;

    for (int i = tid * 4; i < 128 * 128; i += 1024) {
        int r = i >> 7, k = i & 127;
        float4 v = *(const float4*)&q[(size_t)(row0 + r) * NE + k];
        *(float4*)&At[r * 132 + k] =
            make_float4(f2tf_f(v.x), f2tf_f(v.y), f2tf_f(v.z), f2tf_f(v.w));
        float4 w = *(const float4*)&W[(size_t)r * NINNER + col0 + k];
        *(float4*)&Bs[r * 132 + k] =
            make_float4(f2tf_f(w.x), f2tf_f(w.y), f2tf_f(w.z), f2tf_f(w.w));
    }
    __syncthreads();

    float acc[16][4] = {};
    #pragma unroll
    for (int ks = 0; ks < 16; ks++) {
        const float* arow = &At[(wid * 16 + lg) * 132 + ks * 8 + lc];
        uint32_t a0 = __float_as_uint(arow[0]);
        uint32_t a1 = __float_as_uint(arow[8 * 132]);
        uint32_t a2 = __float_as_uint(arow[4]);
        uint32_t a3 = __float_as_uint(arow[8 * 132 + 4]);
        #pragma unroll
        for (int nb = 0; nb < 16; nb++) {
            const float* brow = &Bs[(ks * 8 + lc) * 132 + nb * 8 + lg];
            uint32_t b0 = __float_as_uint(brow[0]);
            uint32_t b1 = __float_as_uint(brow[4 * 132]);
            mma8(acc[nb], a0, a1, a2, a3, b0, b1);
        }
    }

    const float qscale = 0.08838834764831845f * 1.4426950408889634f;
    float oscale = (z == 0) ? qscale : 1.0f;
    bool do_rope = (z < 2);

    int row_a = row0 + wid * 16 + lg;
    int b = row_a >> 11;
    int s0 = row_a & (NS - 1);
    int s1 = s0 + 8;
    __half* d0p = &dst[((size_t)(b * NH + h) * NS + s0) * ND];
    __half* d1p = &dst[((size_t)(b * NH + h) * NS + s1) * ND];

    #pragma unroll
    for (int nb = 0; nb < 16; nb++) {
        int dcol = nb * 8 + 2 * lc;
        int p = nb * 4 + lc;
        float c0 = acc[nb][0], c1 = acc[nb][1];
        float c2 = acc[nb][2], c3 = acc[nb][3];
        if (do_rope) {
            float2 csa = g_rope[s0 * HALF + p];
            float2 csb = g_rope[s1 * HALF + p];
            float r0 = c0 * csa.x - c1 * csa.y;
            float r1 = c1 * csa.x + c0 * csa.y;
            float r2 = c2 * csb.x - c3 * csb.y;
            float r3 = c3 * csb.x + c2 * csb.y;
            c0 = r0; c1 = r1; c2 = r2; c3 = r3;
        }
        *(uint32_t*)&d0p[dcol] = pack2(c0 * oscale, c1 * oscale);
        *(uint32_t*)&d1p[dcol] = pack2(c2 * oscale, c3 * oscale);
    }
}

// ---------------------------------------------------------------------------
// Kernel 2: causal flash attention, fp16 mma (fp32 accum), cp.async pipeline.
// ---------------------------------------------------------------------------
#define PITCHB 272
#define KS_SZ  (64 * PITCHB)
#define KS_OFF 0
#define VS_OFF (2 * KS_SZ)
#define QST_OFF (4 * KS_SZ)
#define ATTN_SMEM (QST_OFF + 128 * PITCHB)

__global__ __launch_bounds__(256, 1) void attn_kernel() {
    extern __shared__ char smem[];
    uint32_t sbase = (uint32_t)__cvta_generic_to_shared(smem);

    int qt = gridDim.x - 1 - blockIdx.x;   // heavy tiles first
    int h = blockIdx.y, b = blockIdx.z;
    const __half* Qg = &g_Qh[((size_t)(b * NH + h) * NS + qt * 128) * ND];
    const __half* Kg = &g_Kh[(size_t)(b * NH + h) * NS * ND];
    const __half* Vg = &g_Vh[(size_t)(b * NH + h) * NS * ND];

    int tid = threadIdx.x;
    int wid = tid >> 5, lane = tid & 31;
    int lg = lane >> 2, lc = lane & 3;

    int nkt = 2 * qt + 2;

    {
        const char* sk = (const char*)Kg;
        const char* sv = (const char*)Vg;
        #pragma unroll
        for (int j = 0; j < 4; j++) {
            int idx = tid + j * 256;
            int r = idx >> 4, c = (idx & 15) << 4;
            cp16(sbase + KS_OFF + r * PITCHB + c, sk + r * 256 + c);
            cp16(sbase + VS_OFF + r * PITCHB + c, sv + r * 256 + c);
        }
        cp_commit();
    }
    #pragma unroll
    for (int j = 0; j < 8; j++) {
        int idx = tid + j * 256;
        int r = idx >> 4, c = (idx & 15) << 4;
        *(uint4*)(smem + QST_OFF + r * PITCHB + c) =
            *(const uint4*)((const char*)Qg + r * 256 + c);
    }
    __syncthreads();

    uint32_t laneQ = ((lane & 7) + ((lane >> 3) & 1) * 8) * PITCHB + ((lane >> 4) & 1) * 16;
    uint32_t laneK = ((lane & 7) + ((lane >> 4) & 1) * 8) * PITCHB + ((lane >> 3) & 1) * 16;
    uint32_t laneV = laneQ;

    uint32_t qa[8][4];
    {
        uint32_t qaddr = sbase + QST_OFF + wid * 16 * PITCHB + laneQ;
        #pragma unroll
        for (int kg = 0; kg < 8; kg++) ldsm_x4(qa[kg], qaddr + kg * 32);
    }

    float oacc[16][4] = {};
    float m0 = -1e30f, m1 = -1e30f, l0 = 0.0f, l1 = 0.0f;
    int row_g0 = qt * 128 + wid * 16 + lg;
    int row_g1 = row_g0 + 8;

    for (int kt = 0; kt < nkt; kt++) {
        cp_wait<0>();
        __syncthreads();

        int buf = kt & 1;
        if (kt + 1 < nkt) {
            const char* sk = (const char*)(Kg + (size_t)(kt + 1) * 64 * ND);
            const char* sv = (const char*)(Vg + (size_t)(kt + 1) * 64 * ND);
            uint32_t kd = sbase + KS_OFF + (1 - buf) * KS_SZ;
            uint32_t vd = sbase + VS_OFF + (1 - buf) * KS_SZ;
            #pragma unroll
            for (int j = 0; j < 4; j++) {
                int idx = tid + j * 256;
                int r = idx >> 4, c = (idx & 15) << 4;
                cp16(kd + r * PITCHB + c, sk + r * 256 + c);
                cp16(vd + r * PITCHB + c, sv + r * 256 + c);
            }
            cp_commit();
        }

        // ---- S = Q @ K^T ----
        uint32_t kbase = sbase + KS_OFF + buf * KS_SZ + laneK;
        float sacc[8][4] = {};
        #pragma unroll
        for (int kg = 0; kg < 8; kg++) {
            #pragma unroll
            for (int nbp = 0; nbp < 4; nbp++) {
                uint32_t br[4];
                ldsm_x4(br, kbase + nbp * (16 * PITCHB) + kg * 32);
                mma16(sacc[2 * nbp],     qa[kg][0], qa[kg][1], qa[kg][2], qa[kg][3], br[0], br[1]);
                mma16(sacc[2 * nbp + 1], qa[kg][0], qa[kg][1], qa[kg][2], qa[kg][3], br[2], br[3]);
            }
        }

        if (kt >= 2 * qt) {
            #pragma unroll
            for (int nb = 0; nb < 8; nb++) {
                int col_g = kt * 64 + nb * 8 + 2 * lc;
                if (col_g     > row_g0) sacc[nb][0] = -1e30f;
                if (col_g + 1 > row_g0) sacc[nb][1] = -1e30f;
                if (col_g     > row_g1) sacc[nb][2] = -1e30f;
                if (col_g + 1 > row_g1) sacc[nb][3] = -1e30f;
            }
        }

        // ---- online softmax (log2 domain) ----
        float mt0 = -1e30f, mt1 = -1e30f;
        #pragma unroll
        for (int nb = 0; nb < 8; nb++) {
            mt0 = fmaxf(mt0, fmaxf(sacc[nb][0], sacc[nb][1]));
            mt1 = fmaxf(mt1, fmaxf(sacc[nb][2], sacc[nb][3]));
        }
        mt0 = fmaxf(mt0, __shfl_xor_sync(0xFFFFFFFFu, mt0, 1));
        mt0 = fmaxf(mt0, __shfl_xor_sync(0xFFFFFFFFu, mt0, 2));
        mt1 = fmaxf(mt1, __shfl_xor_sync(0xFFFFFFFFu, mt1, 1));
        mt1 = fmaxf(mt1, __shfl_xor_sync(0xFFFFFFFFu, mt1, 2));
        float mn0 = fmaxf(m0, mt0), mn1 = fmaxf(m1, mt1);
        float al0 = ex2(m0 - mn0), al1 = ex2(m1 - mn1);
        m0 = mn0; m1 = mn1;

        uint32_t ph[8][2];
        float r0 = 0.0f, r1 = 0.0f;
        #pragma unroll
        for (int nb = 0; nb < 8; nb++) {
            float p0 = ex2(sacc[nb][0] - mn0);
            float p1 = ex2(sacc[nb][1] - mn0);
            float p2 = ex2(sacc[nb][2] - mn1);
            float p3 = ex2(sacc[nb][3] - mn1);
            r0 += p0 + p1; r1 += p2 + p3;
            ph[nb][0] = pack2(p0, p1);
            ph[nb][1] = pack2(p2, p3);
        }
        r0 += __shfl_xor_sync(0xFFFFFFFFu, r0, 1);
        r0 += __shfl_xor_sync(0xFFFFFFFFu, r0, 2);
        r1 += __shfl_xor_sync(0xFFFFFFFFu, r1, 1);
        r1 += __shfl_xor_sync(0xFFFFFFFFu, r1, 2);
        l0 = l0 * al0 + r0;
        l1 = l1 * al1 + r1;

        #pragma unroll
        for (int nb = 0; nb < 16; nb++) {
            oacc[nb][0] *= al0; oacc[nb][1] *= al0;
            oacc[nb][2] *= al1; oacc[nb][3] *= al1;
        }

        // ---- O += P @ V ----
        uint32_t vbase = sbase + VS_OFF + buf * KS_SZ + laneV;
        #pragma unroll
        for (int kg = 0; kg < 4; kg++) {
            uint32_t a0 = ph[2 * kg][0], a1 = ph[2 * kg][1];
            uint32_t a2 = ph[2 * kg + 1][0], a3 = ph[2 * kg + 1][1];
            #pragma unroll
            for (int nbp = 0; nbp < 8; nbp++) {
                uint32_t br[4];
                ldsm_x4t(br, vbase + kg * (16 * PITCHB) + nbp * 32);
                mma16(oacc[2 * nbp],     a0, a1, a2, a3, br[0], br[1]);
                mma16(oacc[2 * nbp + 1], a0, a1, a2, a3, br[2], br[3]);
            }
        }
    }

    // ---- epilogue: write O as half ----
    float inv0 = 1.0f / l0, inv1 = 1.0f / l1;
    __half* Og = &g_Oh[((size_t)(b * NH + h) * NS + qt * 128) * ND];
    #pragma unroll
    for (int nb = 0; nb < 16; nb++) {
        int c = nb * 8 + 2 * lc;
        *(uint32_t*)&Og[(size_t)(wid * 16 + lg) * ND + c] =
            pack2(oacc[nb][0] * inv0, oacc[nb][1] * inv0);
        *(uint32_t*)&Og[(size_t)(wid * 16 + lg + 8) * ND + c] =
            pack2(oacc[nb][2] * inv1, oacc[nb][3] * inv1);
    }
}

// ---------------------------------------------------------------------------
__global__ void zero_kernel(float* __restrict__ out, int n) {
    int i = blockIdx.x * 256 + threadIdx.x;
    if (i * 4 < n) *(float4*)&out[i * 4] = make_float4(0.f, 0.f, 0.f, 0.f);
}

// ---------------------------------------------------------------------------
// Kernel 3: output projection, fp16 mma, split-K x4, cp.async double buffer.
// Per CTA: 64 rows x 128 cols, K slice 512 in chunks of 64.
// 8 warps = 4 row-stripes (16 rows) x 2 col-halves (64 cols).
// ---------------------------------------------------------------------------
#define OA_PITCH 144
#define OB_PITCH 272
#define OA_SZ (64 * OA_PITCH)
#define OB_SZ (64 * OB_PITCH)

__global__ __launch_bounds__(256, 1) void out_kernel(float* __restrict__ out) {
    __shared__ __align__(16) char smem[2 * OA_SZ + 2 * OB_SZ];
    uint32_t sbase = (uint32_t)__cvta_generic_to_shared(smem);
    uint32_t aoff[2] = { 0, OA_SZ };
    uint32_t boff[2] = { 2 * OA_SZ, 2 * OA_SZ + OB_SZ };

    int row0 = blockIdx.y * 64;
    int kz0 = blockIdx.z * (NINNER / 4);
    int tid = threadIdx.x;
    int wid = tid >> 5, lane = tid & 31;
    int lg = lane >> 4 ? 0 : 0;   // placeholder (unused)
    lg = lane >> 2;               // row-in-8 group
    int lc = lane & 3;

    int b = row0 >> 11;
    int s_base = row0 & (NS - 1);

    // stage chunk c into buffer bi
    auto stage = [&](int c, int bi) {
        int kk = kz0 + c * 64;
        int h = kk >> 7, d0 = kk & 127;
        const char* asrc = (const char*)&g_Oh[((size_t)(b * NH + h) * NS + s_base) * ND + d0];
        #pragma unroll
        for (int j = 0; j < 2; j++) {
            int idx = tid + j * 256;
            int r = idx >> 3, cc = (idx & 7) << 4;
            cp16(sbase + aoff[bi] + r * OA_PITCH + cc, asrc + (size_t)r * 256 + cc);
        }
        const char* bsrc = (const char*)&g_Woh[(size_t)kk * NE];
        #pragma unroll
        for (int j = 0; j < 4; j++) {
            int idx = tid + j * 256;
            int r = idx >> 4, cc = (idx & 15) << 4;
            cp16(sbase + boff[bi] + r * OB_PITCH + cc, bsrc + (size_t)r * 256 + cc);
        }
        cp_commit();
    };

    stage(0, 0);

    uint32_t laneA = ((lane & 7) + ((lane >> 3) & 1) * 8) * OA_PITCH + ((lane >> 4) & 1) * 16;
    uint32_t laneB = ((lane & 7) + ((lane >> 3) & 1) * 8) * OB_PITCH + ((lane >> 4) & 1) * 16;

    float acc[8][4] = {};

    for (int c = 0; c < 8; c++) {
        cp_wait<0>();
        __syncthreads();
        int bi = c & 1;
        if (c + 1 < 8) stage(c + 1, 1 - bi);

        uint32_t abase = sbase + aoff[bi] + (wid >> 1) * 16 * OA_PITCH + laneA;
        uint32_t bbase = sbase + boff[bi] + (wid & 1) * 128 + laneB;

        #pragma unroll
        for (int kg = 0; kg < 4; kg++) {
            uint32_t a[4];
            ldsm_x4(a, abase + kg * 32);
            #pragma unroll
            for (int nbp = 0; nbp < 4; nbp++) {
                uint32_t br[4];
                ldsm_x4t(br, bbase + kg * (16 * OB_PITCH) + nbp * 32);
                mma16(acc[2 * nbp],     a[0], a[1], a[2], a[3], br[0], br[1]);
                mma16(acc[2 * nbp + 1], a[0], a[1], a[2], a[3], br[2], br[3]);
            }
        }
        __syncthreads();
    }

    int r0 = row0 + (wid >> 1) * 16 + lg;
    int r1 = r0 + 8;
    int colb = (wid & 1) * 64;
    #pragma unroll
    for (int nb = 0; nb < 8; nb++) {
        int cc = colb + (nb >> 1) * 16 + (nb & 1) * 8 + 2 * lc;
        atomicAdd(&out[(size_t)r0 * NE + cc],     acc[nb][0]);
        atomicAdd(&out[(size_t)r0 * NE + cc + 1], acc[nb][1]);
        atomicAdd(&out[(size_t)r1 * NE + cc],     acc[nb][2]);
        atomicAdd(&out[(size_t)r1 * NE + cc + 1], acc[nb][3]);
    }
}

// ---------------------------------------------------------------------------
extern "C" void kernel_launch(void* const* d_in, const int* in_sizes, int n_in,
                              void* d_out, int out_size) {
    const float* q  = (const float*)d_in[0];
    const float* Wq = (const float*)d_in[1];
    const float* Wk = (const float*)d_in[2];
    const float* Wv = (const float*)d_in[3];
    const float* Wo = (const float*)d_in[4];
    float* out = (float*)d_out;

    cudaFuncSetAttribute(proj_kernel, cudaFuncAttributeMaxDynamicSharedMemorySize, PROJ_SMEM);
    cudaFuncSetAttribute(attn_kernel, cudaFuncAttributeMaxDynamicSharedMemorySize, ATTN_SMEM);

    rope_table_kernel<<<(NS * HALF + 255) / 256, 256>>>();
    wo_half_kernel<<<(NINNER * NE / 4 + 255) / 256, 256>>>(Wo);

    dim3 g1(NINNER / 128, NROWS / 128, 3);
    proj_kernel<<<g1, 256, PROJ_SMEM>>>(q, Wq, Wk, Wv);

    dim3 g2(NS / 128, NH, NB);
    attn_kernel<<<g2, 256, ATTN_SMEM>>>();

    zero_kernel<<<(NROWS * NE / 4 + 255) / 256, 256>>>(out, NROWS * NE);

    dim3 g3(1, NROWS / 64, 4);
    out_kernel<<<g3, 256>>>(out);
}

// round 11
// speedup vs baseline: 9.9919x; 1.3223x over previous
#include <cuda_runtime.h>
#include <cuda_fp16.h>
#include <math.h>
#include <stdint.h>

#define NB 2
#define NS 2048
#define NE 128
#define NH 16
#define ND 128
#define NINNER 2048
#define NROWS 4096
#define HALF 64

// Scratch
__device__ __half g_Qh[NB*NH*NS*ND];
__device__ __half g_Kh[NB*NH*NS*ND];
__device__ __half g_Vh[NB*NH*NS*ND];
__device__ __half g_Oh[NB*NH*NS*ND];
__device__ __half g_Woh[NINNER*NE];
__device__ __half g_Wqh[NE*NINNER];
__device__ __half g_Wkh[NE*NINNER];
__device__ __half g_Wvh[NE*NINNER];
__device__ __half g_qhi[NROWS*NE];
__device__ __half g_qlo[NROWS*NE];
__device__ float2 g_rope[NS*HALF];

// ---------------------------------------------------------------------------
__global__ void rope_table_kernel() {
    int idx = blockIdx.x * 256 + threadIdx.x;
    if (idx >= NS * HALF) return;
    int s = idx / HALF, p = idx % HALF;
    double inv = exp(-(double)p * (log(10000.0) / 64.0));
    double a = (double)s * inv;
    g_rope[idx] = make_float2((float)cos(a), (float)sin(a));
}

// ---------------------------------------------------------------------------
// helpers
// ---------------------------------------------------------------------------
__device__ __forceinline__ void mma16(float* c, uint32_t a0, uint32_t a1,
                                      uint32_t a2, uint32_t a3,
                                      uint32_t b0, uint32_t b1) {
    asm("mma.sync.aligned.m16n8k16.row.col.f32.f16.f16.f32 "
        "{%0,%1,%2,%3},{%4,%5,%6,%7},{%8,%9},{%0,%1,%2,%3};"
        : "+f"(c[0]), "+f"(c[1]), "+f"(c[2]), "+f"(c[3])
        : "r"(a0), "r"(a1), "r"(a2), "r"(a3), "r"(b0), "r"(b1));
}
__device__ __forceinline__ void ldsm_x4(uint32_t* r, uint32_t addr) {
    asm volatile("ldmatrix.sync.aligned.m8n8.x4.shared.b16 {%0,%1,%2,%3}, [%4];"
        : "=r"(r[0]), "=r"(r[1]), "=r"(r[2]), "=r"(r[3]) : "r"(addr));
}
__device__ __forceinline__ void ldsm_x4t(uint32_t* r, uint32_t addr) {
    asm volatile("ldmatrix.sync.aligned.m8n8.x4.trans.shared.b16 {%0,%1,%2,%3}, [%4];"
        : "=r"(r[0]), "=r"(r[1]), "=r"(r[2]), "=r"(r[3]) : "r"(addr));
}
__device__ __forceinline__ float ex2(float x) {
    float y;
    asm("ex2.approx.f32 %0, %1;" : "=f"(y) : "f"(x));
    return y;
}
__device__ __forceinline__ uint32_t h2ex2(uint32_t x) {
    uint32_t y;
    asm("ex2.approx.f16x2 %0, %1;" : "=r"(y) : "r"(x));
    return y;
}
__device__ __forceinline__ uint32_t pack2(float a, float b) {
    __half2 h = __floats2half2_rn(a, b);
    return *(uint32_t*)&h;
}
__device__ __forceinline__ void cp16(uint32_t dst, const void* src) {
    asm volatile("cp.async.cg.shared.global [%0], [%1], 16;"
                 :: "r"(dst), "l"(src));
}
__device__ __forceinline__ void cp_commit() {
    asm volatile("cp.async.commit_group;");
}
template <int N>
__device__ __forceinline__ void cp_wait() {
    asm volatile("cp.async.wait_group %0;" :: "n"(N));
}

// ---------------------------------------------------------------------------
// Kernel 0b: convert a weight matrix to half (z selects Wq/Wk/Wv/Wo)
// ---------------------------------------------------------------------------
__global__ void wconv_kernel(const float* __restrict__ Wq, const float* __restrict__ Wk,
                             const float* __restrict__ Wv, const float* __restrict__ Wo) {
    int z = blockIdx.z;
    const float* src = (z == 0) ? Wq : (z == 1) ? Wk : (z == 2) ? Wv : Wo;
    __half* dst = (z == 0) ? g_Wqh : (z == 1) ? g_Wkh : (z == 2) ? g_Wvh : g_Woh;
    int i = blockIdx.x * 256 + threadIdx.x;     // one float4
    float4 v = *(const float4*)&src[(size_t)i * 4];
    *(uint2*)&dst[(size_t)i * 4] = make_uint2(pack2(v.x, v.y), pack2(v.z, v.w));
}

// ---------------------------------------------------------------------------
// Kernel 0c: split activations q into f16 hi + f16 residual lo
// ---------------------------------------------------------------------------
__global__ void qsplit_kernel(const float* __restrict__ q) {
    int i = blockIdx.x * 256 + threadIdx.x;     // one float4
    float4 v = *(const float4*)&q[(size_t)i * 4];
    __half hx = __float2half_rn(v.x), hy = __float2half_rn(v.y);
    __half hz = __float2half_rn(v.z), hw = __float2half_rn(v.w);
    __half2 h0 = __halves2half2(hx, hy), h1 = __halves2half2(hz, hw);
    *(uint2*)&g_qhi[(size_t)i * 4] = make_uint2(*(uint32_t*)&h0, *(uint32_t*)&h1);
    float lx = v.x - __half2float(hx), ly = v.y - __half2float(hy);
    float lz = v.z - __half2float(hz), lw = v.w - __half2float(hw);
    *(uint2*)&g_qlo[(size_t)i * 4] = make_uint2(pack2(lx, ly), pack2(lz, lw));
}

// ---------------------------------------------------------------------------
// Kernel 1: fused QKV projection, fp16 mma with split-A compensation + RoPE.
// D = Ahi*B + Alo*B (error ~= f16 rounding of W only).
// Per CTA: 128 rows x 128 cols (one head), K=128. 8 warps = 16-row stripes.
// ---------------------------------------------------------------------------
#define PPITCH 272
#define PA_SZ (128 * PPITCH)
#define PROJ_SMEM (3 * PA_SZ)

__global__ __launch_bounds__(256, 1) void proj_kernel() {
    extern __shared__ char psm[];
    uint32_t sbase = (uint32_t)__cvta_generic_to_shared(psm);
    uint32_t ahi_off = 0, alo_off = PA_SZ, b_off = 2 * PA_SZ;

    int z = blockIdx.z;
    const __half* W = (z == 0) ? g_Wqh : (z == 1) ? g_Wkh : g_Wvh;
    __half* dst = (z == 0) ? g_Qh : (z == 1) ? g_Kh : g_Vh;

    int h = blockIdx.x;
    int row0 = blockIdx.y * 128;
    int col0 = h * 128;
    int tid = threadIdx.x;
    int wid = tid >> 5, lane = tid & 31;
    int lg = lane >> 2, lc = lane & 3;

    // stage Ahi, Alo, B via cp.async (each 128 rows x 256 B)
    #pragma unroll
    for (int j = 0; j < 8; j++) {
        int idx = tid + j * 256;
        int r = idx >> 4, c = (idx & 15) << 4;
        cp16(sbase + ahi_off + r * PPITCH + c,
             (const char*)&g_qhi[(size_t)(row0 + r) * NE] + c);
        cp16(sbase + alo_off + r * PPITCH + c,
             (const char*)&g_qlo[(size_t)(row0 + r) * NE] + c);
        cp16(sbase + b_off + r * PPITCH + c,
             (const char*)&W[(size_t)r * NINNER + col0] + c);
    }
    cp_commit();
    cp_wait<0>();
    __syncthreads();

    uint32_t laneQ = ((lane & 7) + ((lane >> 3) & 1) * 8) * PPITCH + ((lane >> 4) & 1) * 16;

    uint32_t ahi[8][4], alo[8][4];
    {
        uint32_t abase_h = sbase + ahi_off + wid * 16 * PPITCH + laneQ;
        uint32_t abase_l = sbase + alo_off + wid * 16 * PPITCH + laneQ;
        #pragma unroll
        for (int kg = 0; kg < 8; kg++) {
            ldsm_x4(ahi[kg], abase_h + kg * 32);
            ldsm_x4(alo[kg], abase_l + kg * 32);
        }
    }

    float acc[16][4] = {};
    uint32_t bbase = sbase + b_off + laneQ;
    #pragma unroll
    for (int kg = 0; kg < 8; kg++) {
        #pragma unroll
        for (int nbp = 0; nbp < 8; nbp++) {
            uint32_t br[4];
            ldsm_x4t(br, bbase + kg * (16 * PPITCH) + nbp * 32);
            mma16(acc[2 * nbp],     ahi[kg][0], ahi[kg][1], ahi[kg][2], ahi[kg][3], br[0], br[1]);
            mma16(acc[2 * nbp],     alo[kg][0], alo[kg][1], alo[kg][2], alo[kg][3], br[0], br[1]);
            mma16(acc[2 * nbp + 1], ahi[kg][0], ahi[kg][1], ahi[kg][2], ahi[kg][3], br[2], br[3]);
            mma16(acc[2 * nbp + 1], alo[kg][0], alo[kg][1], alo[kg][2], alo[kg][3], br[2], br[3]);
        }
    }

    const float qscale = 0.08838834764831845f * 1.4426950408889634f;
    float oscale = (z == 0) ? qscale : 1.0f;
    bool do_rope = (z < 2);

    int row_a = row0 + wid * 16 + lg;
    int b = row_a >> 11;
    int s0 = row_a & (NS - 1);
    int s1 = s0 + 8;
    __half* d0p = &dst[((size_t)(b * NH + h) * NS + s0) * ND];
    __half* d1p = &dst[((size_t)(b * NH + h) * NS + s1) * ND];

    #pragma unroll
    for (int nb = 0; nb < 16; nb++) {
        int dcol = nb * 8 + 2 * lc;
        int p = nb * 4 + lc;
        float c0 = acc[nb][0], c1 = acc[nb][1];
        float c2 = acc[nb][2], c3 = acc[nb][3];
        if (do_rope) {
            float2 csa = g_rope[s0 * HALF + p];
            float2 csb = g_rope[s1 * HALF + p];
            float r0 = c0 * csa.x - c1 * csa.y;
            float r1 = c1 * csa.x + c0 * csa.y;
            float r2 = c2 * csb.x - c3 * csb.y;
            float r3 = c3 * csb.x + c2 * csb.y;
            c0 = r0; c1 = r1; c2 = r2; c3 = r3;
        }
        *(uint32_t*)&d0p[dcol] = pack2(c0 * oscale, c1 * oscale);
        *(uint32_t*)&d1p[dcol] = pack2(c2 * oscale, c3 * oscale);
    }
}

// ---------------------------------------------------------------------------
// Kernel 2: causal flash attention, fp16 mma, cp.async pipeline.
// Softmax: f16x2 ex2; row-sum l via ones-fragment mma (auto alpha-rescaled).
// ---------------------------------------------------------------------------
#define PITCHB 272
#define KS_SZ  (64 * PITCHB)
#define KS_OFF 0
#define VS_OFF (2 * KS_SZ)
#define QST_OFF (4 * KS_SZ)
#define ATTN_SMEM (QST_OFF + 128 * PITCHB)

__global__ __launch_bounds__(256, 1) void attn_kernel() {
    extern __shared__ char smem[];
    uint32_t sbase = (uint32_t)__cvta_generic_to_shared(smem);

    int qt = gridDim.x - 1 - blockIdx.x;   // heavy tiles first
    int h = blockIdx.y, b = blockIdx.z;
    const __half* Qg = &g_Qh[((size_t)(b * NH + h) * NS + qt * 128) * ND];
    const __half* Kg = &g_Kh[(size_t)(b * NH + h) * NS * ND];
    const __half* Vg = &g_Vh[(size_t)(b * NH + h) * NS * ND];

    int tid = threadIdx.x;
    int wid = tid >> 5, lane = tid & 31;
    int lg = lane >> 2, lc = lane & 3;

    int nkt = 2 * qt + 2;
    uint32_t ones_b = (lg == 0) ? 0x3C003C00u : 0u;   // B frag: col n=0 all ones

    {
        const char* sk = (const char*)Kg;
        const char* sv = (const char*)Vg;
        #pragma unroll
        for (int j = 0; j < 4; j++) {
            int idx = tid + j * 256;
            int r = idx >> 4, c = (idx & 15) << 4;
            cp16(sbase + KS_OFF + r * PITCHB + c, sk + r * 256 + c);
            cp16(sbase + VS_OFF + r * PITCHB + c, sv + r * 256 + c);
        }
        cp_commit();
    }
    #pragma unroll
    for (int j = 0; j < 8; j++) {
        int idx = tid + j * 256;
        int r = idx >> 4, c = (idx & 15) << 4;
        *(uint4*)(smem + QST_OFF + r * PITCHB + c) =
            *(const uint4*)((const char*)Qg + r * 256 + c);
    }
    __syncthreads();

    uint32_t laneQ = ((lane & 7) + ((lane >> 3) & 1) * 8) * PITCHB + ((lane >> 4) & 1) * 16;
    uint32_t laneK = ((lane & 7) + ((lane >> 4) & 1) * 8) * PITCHB + ((lane >> 3) & 1) * 16;
    uint32_t laneV = laneQ;

    uint32_t qa[8][4];
    {
        uint32_t qaddr = sbase + QST_OFF + wid * 16 * PITCHB + laneQ;
        #pragma unroll
        for (int kg = 0; kg < 8; kg++) ldsm_x4(qa[kg], qaddr + kg * 32);
    }

    float oacc[16][4] = {};
    float lrow[4] = {};
    float m0 = -1e30f, m1 = -1e30f;
    int row_g0 = qt * 128 + wid * 16 + lg;
    int row_g1 = row_g0 + 8;

    for (int kt = 0; kt < nkt; kt++) {
        cp_wait<0>();
        __syncthreads();

        int buf = kt & 1;
        if (kt + 1 < nkt) {
            const char* sk = (const char*)(Kg + (size_t)(kt + 1) * 64 * ND);
            const char* sv = (const char*)(Vg + (size_t)(kt + 1) * 64 * ND);
            uint32_t kd = sbase + KS_OFF + (1 - buf) * KS_SZ;
            uint32_t vd = sbase + VS_OFF + (1 - buf) * KS_SZ;
            #pragma unroll
            for (int j = 0; j < 4; j++) {
                int idx = tid + j * 256;
                int r = idx >> 4, c = (idx & 15) << 4;
                cp16(kd + r * PITCHB + c, sk + r * 256 + c);
                cp16(vd + r * PITCHB + c, sv + r * 256 + c);
            }
            cp_commit();
        }

        // ---- S = Q @ K^T ----
        uint32_t kbase = sbase + KS_OFF + buf * KS_SZ + laneK;
        float sacc[8][4] = {};
        #pragma unroll
        for (int kg = 0; kg < 8; kg++) {
            #pragma unroll
            for (int nbp = 0; nbp < 4; nbp++) {
                uint32_t br[4];
                ldsm_x4(br, kbase + nbp * (16 * PITCHB) + kg * 32);
                mma16(sacc[2 * nbp],     qa[kg][0], qa[kg][1], qa[kg][2], qa[kg][3], br[0], br[1]);
                mma16(sacc[2 * nbp + 1], qa[kg][0], qa[kg][1], qa[kg][2], qa[kg][3], br[2], br[3]);
            }
        }

        if (kt >= 2 * qt) {
            #pragma unroll
            for (int nb = 0; nb < 8; nb++) {
                int col_g = kt * 64 + nb * 8 + 2 * lc;
                if (col_g     > row_g0) sacc[nb][0] = -1e30f;
                if (col_g + 1 > row_g0) sacc[nb][1] = -1e30f;
                if (col_g     > row_g1) sacc[nb][2] = -1e30f;
                if (col_g + 1 > row_g1) sacc[nb][3] = -1e30f;
            }
        }

        // ---- online softmax (log2 domain) ----
        float mt0 = -1e30f, mt1 = -1e30f;
        #pragma unroll
        for (int nb = 0; nb < 8; nb++) {
            mt0 = fmaxf(mt0, fmaxf(sacc[nb][0], sacc[nb][1]));
            mt1 = fmaxf(mt1, fmaxf(sacc[nb][2], sacc[nb][3]));
        }
        mt0 = fmaxf(mt0, __shfl_xor_sync(0xFFFFFFFFu, mt0, 1));
        mt0 = fmaxf(mt0, __shfl_xor_sync(0xFFFFFFFFu, mt0, 2));
        mt1 = fmaxf(mt1, __shfl_xor_sync(0xFFFFFFFFu, mt1, 1));
        mt1 = fmaxf(mt1, __shfl_xor_sync(0xFFFFFFFFu, mt1, 2));
        float mn0 = fmaxf(m0, mt0), mn1 = fmaxf(m1, mt1);
        float al0 = ex2(m0 - mn0), al1 = ex2(m1 - mn1);
        m0 = mn0; m1 = mn1;

        // p = 2^(s-m) directly in f16x2
        uint32_t ph[8][2];
        #pragma unroll
        for (int nb = 0; nb < 8; nb++) {
            ph[nb][0] = h2ex2(pack2(sacc[nb][0] - mn0, sacc[nb][1] - mn0));
            ph[nb][1] = h2ex2(pack2(sacc[nb][2] - mn1, sacc[nb][3] - mn1));
        }

        // rescale O and l
        #pragma unroll
        for (int nb = 0; nb < 16; nb++) {
            oacc[nb][0] *= al0; oacc[nb][1] *= al0;
            oacc[nb][2] *= al1; oacc[nb][3] *= al1;
        }
        lrow[0] *= al0; lrow[1] *= al0; lrow[2] *= al1; lrow[3] *= al1;

        // l += P @ ones (constant B fragment, no smem)
        #pragma unroll
        for (int kg = 0; kg < 4; kg++)
            mma16(lrow, ph[2 * kg][0], ph[2 * kg][1],
                  ph[2 * kg + 1][0], ph[2 * kg + 1][1], ones_b, ones_b);

        // ---- O += P @ V ----
        uint32_t vbase = sbase + VS_OFF + buf * KS_SZ + laneV;
        #pragma unroll
        for (int kg = 0; kg < 4; kg++) {
            uint32_t a0 = ph[2 * kg][0], a1 = ph[2 * kg][1];
            uint32_t a2 = ph[2 * kg + 1][0], a3 = ph[2 * kg + 1][1];
            #pragma unroll
            for (int nbp = 0; nbp < 8; nbp++) {
                uint32_t br[4];
                ldsm_x4t(br, vbase + kg * (16 * PITCHB) + nbp * 32);
                mma16(oacc[2 * nbp],     a0, a1, a2, a3, br[0], br[1]);
                mma16(oacc[2 * nbp + 1], a0, a1, a2, a3, br[2], br[3]);
            }
        }
    }

    // ---- epilogue: l lives at n=0 (lc==0 lanes) of lrow ----
    float lt0 = __shfl_sync(0xFFFFFFFFu, lrow[0], lane & 28);
    float lt1 = __shfl_sync(0xFFFFFFFFu, lrow[2], lane & 28);
    float inv0 = 1.0f / lt0, inv1 = 1.0f / lt1;
    __half* Og = &g_Oh[((size_t)(b * NH + h) * NS + qt * 128) * ND];
    #pragma unroll
    for (int nb = 0; nb < 16; nb++) {
        int c = nb * 8 + 2 * lc;
        *(uint32_t*)&Og[(size_t)(wid * 16 + lg) * ND + c] =
            pack2(oacc[nb][0] * inv0, oacc[nb][1] * inv0);
        *(uint32_t*)&Og[(size_t)(wid * 16 + lg + 8) * ND + c] =
            pack2(oacc[nb][2] * inv1, oacc[nb][3] * inv1);
    }
}

// ---------------------------------------------------------------------------
__global__ void zero_kernel(float* __restrict__ out, int n) {
    int i = blockIdx.x * 256 + threadIdx.x;
    if (i * 4 < n) *(float4*)&out[i * 4] = make_float4(0.f, 0.f, 0.f, 0.f);
}

// ---------------------------------------------------------------------------
// Kernel 3: output projection, fp16 mma, split-K x4, cp.async double buffer.
// ---------------------------------------------------------------------------
#define OA_PITCH 144
#define OB_PITCH 272
#define OA_SZ (64 * OA_PITCH)
#define OB_SZ (64 * OB_PITCH)

__global__ __launch_bounds__(256, 1) void out_kernel(float* __restrict__ out) {
    __shared__ __align__(16) char smem[2 * OA_SZ + 2 * OB_SZ];
    uint32_t sbase = (uint32_t)__cvta_generic_to_shared(smem);
    uint32_t aoff[2] = { 0, OA_SZ };
    uint32_t boff[2] = { 2 * OA_SZ, 2 * OA_SZ + OB_SZ };

    int row0 = blockIdx.y * 64;
    int kz0 = blockIdx.z * (NINNER / 4);
    int tid = threadIdx.x;
    int wid = tid >> 5, lane = tid & 31;
    int lg = lane >> 2, lc = lane & 3;

    int b = row0 >> 11;
    int s_base = row0 & (NS - 1);

    auto stage = [&](int c, int bi) {
        int kk = kz0 + c * 64;
        int h = kk >> 7, d0 = kk & 127;
        const char* asrc = (const char*)&g_Oh[((size_t)(b * NH + h) * NS + s_base) * ND + d0];
        #pragma unroll
        for (int j = 0; j < 2; j++) {
            int idx = tid + j * 256;
            int r = idx >> 3, cc = (idx & 7) << 4;
            cp16(sbase + aoff[bi] + r * OA_PITCH + cc, asrc + (size_t)r * 256 + cc);
        }
        const char* bsrc = (const char*)&g_Woh[(size_t)kk * NE];
        #pragma unroll
        for (int j = 0; j < 4; j++) {
            int idx = tid + j * 256;
            int r = idx >> 4, cc = (idx & 15) << 4;
            cp16(sbase + boff[bi] + r * OB_PITCH + cc, bsrc + (size_t)r * 256 + cc);
        }
        cp_commit();
    };

    stage(0, 0);

    uint32_t laneA = ((lane & 7) + ((lane >> 3) & 1) * 8) * OA_PITCH + ((lane >> 4) & 1) * 16;
    uint32_t laneB = ((lane & 7) + ((lane >> 3) & 1) * 8) * OB_PITCH + ((lane >> 4) & 1) * 16;

    float acc[8][4] = {};

    for (int c = 0; c < 8; c++) {
        cp_wait<0>();
        __syncthreads();
        int bi = c & 1;
        if (c + 1 < 8) stage(c + 1, 1 - bi);

        uint32_t abase = sbase + aoff[bi] + (wid >> 1) * 16 * OA_PITCH + laneA;
        uint32_t bbase = sbase + boff[bi] + (wid & 1) * 128 + laneB;

        #pragma unroll
        for (int kg = 0; kg < 4; kg++) {
            uint32_t a[4];
            ldsm_x4(a, abase + kg * 32);
            #pragma unroll
            for (int nbp = 0; nbp < 4; nbp++) {
                uint32_t br[4];
                ldsm_x4t(br, bbase + kg * (16 * OB_PITCH) + nbp * 32);
                mma16(acc[2 * nbp],     a[0], a[1], a[2], a[3], br[0], br[1]);
                mma16(acc[2 * nbp + 1], a[0], a[1], a[2], a[3], br[2], br[3]);
            }
        }
        __syncthreads();
    }

    int r0 = row0 + (wid >> 1) * 16 + lg;
    int r1 = r0 + 8;
    int colb = (wid & 1) * 64;
    #pragma unroll
    for (int nb = 0; nb < 8; nb++) {
        int cc = colb + (nb >> 1) * 16 + (nb & 1) * 8 + 2 * lc;
        atomicAdd(&out[(size_t)r0 * NE + cc],     acc[nb][0]);
        atomicAdd(&out[(size_t)r0 * NE + cc + 1], acc[nb][1]);
        atomicAdd(&out[(size_t)r1 * NE + cc],     acc[nb][2]);
        atomicAdd(&out[(size_t)r1 * NE + cc + 1], acc[nb][3]);
    }
}

// ---------------------------------------------------------------------------
extern "C" void kernel_launch(void* const* d_in, const int* in_sizes, int n_in,
                              void* d_out, int out_size) {
    const float* q  = (const float*)d_in[0];
    const float* Wq = (const float*)d_in[1];
    const float* Wk = (const float*)d_in[2];
    const float* Wv = (const float*)d_in[3];
    const float* Wo = (const float*)d_in[4];
    float* out = (float*)d_out;

    cudaFuncSetAttribute(proj_kernel, cudaFuncAttributeMaxDynamicSharedMemorySize, PROJ_SMEM);
    cudaFuncSetAttribute(attn_kernel, cudaFuncAttributeMaxDynamicSharedMemorySize, ATTN_SMEM);

    rope_table_kernel<<<(NS * HALF + 255) / 256, 256>>>();

    dim3 gw(NE * NINNER / 4 / 256, 1, 4);
    wconv_kernel<<<gw, 256>>>(Wq, Wk, Wv, Wo);
    qsplit_kernel<<<NROWS * NE / 4 / 256, 256>>>(q);

    dim3 g1(NINNER / 128, NROWS / 128, 3);
    proj_kernel<<<g1, 256, PROJ_SMEM>>>();

    dim3 g2(NS / 128, NH, NB);
    attn_kernel<<<g2, 256, ATTN_SMEM>>>();

    zero_kernel<<<(NROWS * NE / 4 + 255) / 256, 256>>>(out, NROWS * NE);

    dim3 g3(1, NROWS / 64, 4);
    out_kernel<<<g3, 256>>>(out);
}